// round 5
// baseline (speedup 1.0000x reference)
#include <cuda_runtime.h>
#include <math.h>
#include <stdint.h>

// Problem dims (fixed by the reference)
static constexpr int S_   = 1024;
static constexpr int D_   = 1024;
static constexpr int H_   = 16;
static constexpr int HD_  = 64;
static constexpr int NL_  = 6;
static constexpr int DFF_ = 4096;
static constexpr float EPS_ = 1.1920929e-07f;

// ---------------- scratch (static device globals; no allocations) ----------
__device__ float g_x [S_*D_];
__device__ float g_x0[S_*D_];
__device__ float g_xl[S_*D_];
__device__ float g_xn[S_*D_];
__device__ float g_q [S_*D_];
__device__ float g_k [S_*D_];
__device__ float g_v [S_*D_];
__device__ float g_v1[S_*D_];
__device__ float g_y [S_*D_];
__device__ float g_h [S_*DFF_];
__device__ float g_sc[(size_t)H_*S_*S_];   // 64 MB scores
__device__ int   g_cpad[S_+1];

// ---------------- mask prefix (cumsum of levels==0) ------------------------
__global__ void build_cpad(const int* __restrict__ levels, int* __restrict__ cpad){
    __shared__ int sbuf[S_];
    int t = threadIdx.x;
    sbuf[t] = (levels[t] == 0) ? 1 : 0;
    __syncthreads();
    for (int off = 1; off < S_; off <<= 1){
        int v = 0;
        if (t >= off) v = sbuf[t - off];
        __syncthreads();
        sbuf[t] += v;
        __syncthreads();
    }
    cpad[t+1] = sbuf[t];
    if (t == 0) cpad[0] = 0;
}

// ---------------- row RMS norm (row = 1024 elems) ---------------------------
__global__ void rms_kernel(const float* __restrict__ in, float* __restrict__ out,
                           float* __restrict__ out2){
    __shared__ float red[256];
    const int row = blockIdx.x;
    const int t = threadIdx.x;
    const float* r = in + (size_t)row * D_;
    float v[4]; float ss = 0.f;
#pragma unroll
    for (int j = 0; j < 4; j++){ v[j] = r[t + j*256]; ss += v[j]*v[j]; }
    red[t] = ss; __syncthreads();
    for (int o = 128; o > 0; o >>= 1){ if (t < o) red[t] += red[t+o]; __syncthreads(); }
    const float sc = rsqrtf(red[0] * (1.f/D_) + EPS_);
    float* o1 = out + (size_t)row * D_;
#pragma unroll
    for (int j = 0; j < 4; j++){
        float w = v[j] * sc;
        o1[t + j*256] = w;
        if (out2) out2[(size_t)row*D_ + t + j*256] = w;
    }
}

// ---------------- xl = l0*x + l1*x0 ; xn = rms(xl) --------------------------
__global__ void mix_rms_kernel(const float* __restrict__ x, const float* __restrict__ x0,
                               const float* __restrict__ lambdas, int layer,
                               float* __restrict__ xl, float* __restrict__ xn){
    __shared__ float red[256];
    const int row = blockIdx.x;
    const int t = threadIdx.x;
    const float l0 = lambdas[2*layer + 0];
    const float l1 = lambdas[2*layer + 1];
    float v[4]; float ss = 0.f;
#pragma unroll
    for (int j = 0; j < 4; j++){
        size_t idx = (size_t)row*D_ + t + j*256;
        float w = l0 * x[idx] + l1 * x0[idx];
        v[j] = w; xl[idx] = w; ss += w*w;
    }
    red[t] = ss; __syncthreads();
    for (int o = 128; o > 0; o >>= 1){ if (t < o) red[t] += red[t+o]; __syncthreads(); }
    const float sc = rsqrtf(red[0] * (1.f/D_) + EPS_);
#pragma unroll
    for (int j = 0; j < 4; j++){
        size_t idx = (size_t)row*D_ + t + j*256;
        xn[idx] = v[j] * sc;
    }
}

// ---------------- generic NT SGEMM: C = A * B^T (+ epilogue) ----------------
// A: [M,K] row-major, B: [N,K] row-major. EPI: 0=none, 1=C=acc+Cadd, 2=relu^2
template<int BM, int BN, int TM, int TN, int EPI>
__device__ __forceinline__ void gemm_body(
    const float* __restrict__ A, const float* __restrict__ B,
    const float* __restrict__ Cadd, float* __restrict__ C,
    int N, int K)
{
    constexpr int BK = 8;
    __shared__ float As[BK][BM+4];
    __shared__ float Bs[BK][BN+4];
    const int bm = blockIdx.y * BM;
    const int bn = blockIdx.x * BN;
    const int tid = threadIdx.x;       // 256 threads
    const int tx = tid & 15;
    const int ty = tid >> 4;

    float acc[TM][TN];
#pragma unroll
    for (int i = 0; i < TM; i++)
#pragma unroll
        for (int j = 0; j < TN; j++) acc[i][j] = 0.f;

    for (int k0 = 0; k0 < K; k0 += BK){
        for (int i = tid; i < BM*2; i += 256){
            int r = i >> 1, c = (i & 1) * 4;
            float4 a = *(const float4*)(A + (size_t)(bm + r)*K + k0 + c);
            As[c+0][r] = a.x; As[c+1][r] = a.y; As[c+2][r] = a.z; As[c+3][r] = a.w;
        }
        for (int i = tid; i < BN*2; i += 256){
            int r = i >> 1, c = (i & 1) * 4;
            float4 b = *(const float4*)(B + (size_t)(bn + r)*K + k0 + c);
            Bs[c+0][r] = b.x; Bs[c+1][r] = b.y; Bs[c+2][r] = b.z; Bs[c+3][r] = b.w;
        }
        __syncthreads();
#pragma unroll
        for (int kk = 0; kk < BK; kk++){
            float ra[TM], rb[TN];
            const float4* ap = (const float4*)(&As[kk][ty*TM]);
#pragma unroll
            for (int i = 0; i < TM/4; i++){
                float4 t4 = ap[i];
                ra[i*4+0]=t4.x; ra[i*4+1]=t4.y; ra[i*4+2]=t4.z; ra[i*4+3]=t4.w;
            }
            const float4* bp = (const float4*)(&Bs[kk][tx*TN]);
#pragma unroll
            for (int j = 0; j < TN/4; j++){
                float4 t4 = bp[j];
                rb[j*4+0]=t4.x; rb[j*4+1]=t4.y; rb[j*4+2]=t4.z; rb[j*4+3]=t4.w;
            }
#pragma unroll
            for (int i = 0; i < TM; i++)
#pragma unroll
                for (int j = 0; j < TN; j++)
                    acc[i][j] = fmaf(ra[i], rb[j], acc[i][j]);
        }
        __syncthreads();
    }

#pragma unroll
    for (int i = 0; i < TM; i++){
        int m = bm + ty*TM + i;
#pragma unroll
        for (int j = 0; j < TN; j++){
            int n = bn + tx*TN + j;
            float v = acc[i][j];
            if (EPI == 1) v += Cadd[(size_t)m*N + n];
            if (EPI == 2) v = (v > 0.f) ? v*v : 0.f;
            C[(size_t)m*N + n] = v;
        }
    }
}

template<int BM, int BN, int TM, int TN, int EPI>
__global__ void gemm_nt(const float* __restrict__ A, const float* __restrict__ B,
                        const float* __restrict__ Cadd, float* __restrict__ C,
                        int N, int K){
    gemm_body<BM,BN,TM,TN,EPI>(A, B, Cadd, C, N, K);
}

// fused Q/K/V projection: blockIdx.z selects weight + output
__global__ void gemm_nt3(const float* __restrict__ A,
                         const float* __restrict__ B0, const float* __restrict__ B1,
                         const float* __restrict__ B2,
                         float* __restrict__ C0, float* __restrict__ C1, float* __restrict__ C2,
                         int N, int K){
    const float* B = (blockIdx.z == 0) ? B0 : (blockIdx.z == 1 ? B1 : B2);
    float*       C = (blockIdx.z == 0) ? C0 : (blockIdx.z == 1 ? C1 : C2);
    gemm_body<128,128,8,8,0>(A, B, nullptr, C, N, K);
}

// ---------------- value residual mix ---------------------------------------
__global__ void vmix_kernel(float* __restrict__ v, float* __restrict__ v1,
                            const float* __restrict__ lamb, int layer, int first){
    int i = blockIdx.x * 256 + threadIdx.x;
    if (first){
        v1[i] = v[i];                 // layer 0: v1 = v, mix is identity
    } else {
        float l = lamb[layer];
        v[i] = (1.f - l) * v[i] + l * v1[i];
    }
}

// ---------------- per-head RMS + RoPE on q and k ----------------------------
// one warp per (t, h); lane j owns the rope pair (j, j+32)
__global__ void qk_rmsrope(float* __restrict__ q, float* __restrict__ k){
    const int gw   = (blockIdx.x * blockDim.x + threadIdx.x) >> 5;  // 0..16383
    const int lane = threadIdx.x & 31;
    const int t = gw >> 4;
    const int h = gw & 15;

    const float inv = expf(-((float)(2*lane) / 64.f) * logf(10000.f));
    const float fr  = (float)t * inv;
    float sn, cs;
    sincosf(fr, &sn, &cs);

    float* bases[2] = { q + (size_t)t*D_ + h*HD_, k + (size_t)t*D_ + h*HD_ };
#pragma unroll
    for (int p = 0; p < 2; p++){
        float* r = bases[p];
        float x1 = r[lane];
        float x2 = r[lane + 32];
        float ss = x1*x1 + x2*x2;
#pragma unroll
        for (int off = 16; off > 0; off >>= 1)
            ss += __shfl_xor_sync(0xffffffffu, ss, off);
        float sc = rsqrtf(ss * (1.f/HD_) + EPS_);
        x1 *= sc; x2 *= sc;
        r[lane]      =  x1*cs + x2*sn;
        r[lane + 32] = -x1*sn + x2*cs;
    }
}

// ---------------- masked scaled scores: S[h][q][k] --------------------------
// grid (kt=16, qt=16, h=16), block 256; each thread 4x4 of a 64x64 tile
__global__ void attn_scores(const float* __restrict__ q, const float* __restrict__ k,
                            const int* __restrict__ levels, const int* __restrict__ samp,
                            const int* __restrict__ cpad, float* __restrict__ scores){
    const int h  = blockIdx.z;
    const int qt = blockIdx.y;
    const int kt = blockIdx.x;
    const int tid = threadIdx.x;
    const int tx = tid & 15, ty = tid >> 4;
    float* Sp = scores + ((size_t)h*S_ + qt*64)*S_ + kt*64;

    if (kt > qt){ // fully above diagonal: all masked
#pragma unroll
        for (int i = 0; i < 4; i++)
#pragma unroll
            for (int j = 0; j < 4; j++)
                Sp[(size_t)(ty*4+i)*S_ + tx*4+j] = -1e30f;
        return;
    }

    __shared__ float Qs[64][65];
    __shared__ float Ks[64][65];
    for (int i = tid; i < 64*16; i += 256){
        int r = i >> 4, c = (i & 15) << 2;
        float4 qv = *(const float4*)(q + (size_t)(qt*64 + r)*D_ + h*HD_ + c);
        Qs[r][c+0]=qv.x; Qs[r][c+1]=qv.y; Qs[r][c+2]=qv.z; Qs[r][c+3]=qv.w;
        float4 kv = *(const float4*)(k + (size_t)(kt*64 + r)*D_ + h*HD_ + c);
        Ks[r][c+0]=kv.x; Ks[r][c+1]=kv.y; Ks[r][c+2]=kv.z; Ks[r][c+3]=kv.w;
    }
    __syncthreads();

    float acc[4][4];
#pragma unroll
    for (int i=0;i<4;i++)
#pragma unroll
        for (int j=0;j<4;j++) acc[i][j]=0.f;

#pragma unroll 8
    for (int d = 0; d < 64; d++){
        float ra[4], rb[4];
#pragma unroll
        for (int i = 0; i < 4; i++) ra[i] = Qs[ty*4+i][d];
#pragma unroll
        for (int j = 0; j < 4; j++) rb[j] = Ks[tx*4+j][d];
#pragma unroll
        for (int i = 0; i < 4; i++)
#pragma unroll
            for (int j = 0; j < 4; j++)
                acc[i][j] = fmaf(ra[i], rb[j], acc[i][j]);
    }

    const float scale = 0.125f;  // HD^-0.5
#pragma unroll
    for (int i = 0; i < 4; i++){
        int qq = qt*64 + ty*4 + i;
#pragma unroll
        for (int j = 0; j < 4; j++){
            int kk = kt*64 + tx*4 + j;
            bool ok = (kk <= qq)
                   && (samp[kk] == samp[qq])
                   && !((levels[kk] == 0) && (cpad[qq] - cpad[kk+1] > 0));
            Sp[(size_t)(ty*4+i)*S_ + tx*4+j] = ok ? acc[i][j]*scale : -1e30f;
        }
    }
}

// ---------------- row softmax over K=1024 -----------------------------------
__global__ void softmax_kernel(float* __restrict__ sc){
    __shared__ float red[256];
    const size_t row = blockIdx.x;
    float* p = sc + row * S_;
    const int t = threadIdx.x;
    float v[4];
    float mx = -1e38f;
#pragma unroll
    for (int j = 0; j < 4; j++){ v[j] = p[t + j*256]; mx = fmaxf(mx, v[j]); }
    red[t] = mx; __syncthreads();
    for (int o = 128; o > 0; o >>= 1){ if (t < o) red[t] = fmaxf(red[t], red[t+o]); __syncthreads(); }
    mx = red[0]; __syncthreads();
    float s = 0.f;
#pragma unroll
    for (int j = 0; j < 4; j++){ v[j] = __expf(v[j] - mx); s += v[j]; }
    red[t] = s; __syncthreads();
    for (int o = 128; o > 0; o >>= 1){ if (t < o) red[t] += red[t+o]; __syncthreads(); }
    const float inv = 1.f / red[0];
#pragma unroll
    for (int j = 0; j < 4; j++) p[t + j*256] = v[j] * inv;
}

// ---------------- y[t][h*64+d] = sum_k P[h][t][k] * v[k][h*64+d] ------------
// grid (qt=16, h=16), block 256; 64 rows x 64 cols per block, K in 16-chunks
__global__ void attn_out(const float* __restrict__ scores, const float* __restrict__ v,
                         float* __restrict__ y){
    const int h  = blockIdx.y;
    const int qt = blockIdx.x;
    const int tid = threadIdx.x;
    const int tx = tid & 15, ty = tid >> 4;

    __shared__ float Ps[64][17];
    __shared__ float Vs[16][68];

    float acc[4][4];
#pragma unroll
    for (int i=0;i<4;i++)
#pragma unroll
        for (int j=0;j<4;j++) acc[i][j]=0.f;

    const float* Sp = scores + ((size_t)h*S_ + qt*64)*S_;

    for (int k0 = 0; k0 < S_; k0 += 16){
        {   // load P tile 64x16 (one float4/thread)
            int r = tid >> 2, c = (tid & 3) << 2;
            float4 pv = *(const float4*)(Sp + (size_t)r*S_ + k0 + c);
            Ps[r][c+0]=pv.x; Ps[r][c+1]=pv.y; Ps[r][c+2]=pv.z; Ps[r][c+3]=pv.w;
        }
        {   // load V tile 16x64 (one float4/thread)
            int r = tid >> 4, c = (tid & 15) << 2;
            float4 vv = *(const float4*)(v + (size_t)(k0 + r)*D_ + h*HD_ + c);
            Vs[r][c+0]=vv.x; Vs[r][c+1]=vv.y; Vs[r][c+2]=vv.z; Vs[r][c+3]=vv.w;
        }
        __syncthreads();
#pragma unroll
        for (int kk = 0; kk < 16; kk++){
            float ra[4];
#pragma unroll
            for (int i = 0; i < 4; i++) ra[i] = Ps[ty*4+i][kk];
            const float4* bp = (const float4*)(&Vs[kk][tx*4]);
            float4 b4 = bp[0];
            float rb[4] = { b4.x, b4.y, b4.z, b4.w };
#pragma unroll
            for (int i = 0; i < 4; i++)
#pragma unroll
                for (int j = 0; j < 4; j++)
                    acc[i][j] = fmaf(ra[i], rb[j], acc[i][j]);
        }
        __syncthreads();
    }

#pragma unroll
    for (int i = 0; i < 4; i++){
        int t = qt*64 + ty*4 + i;
#pragma unroll
        for (int j = 0; j < 4; j++)
            y[(size_t)t*D_ + h*HD_ + tx*4 + j] = acc[i][j];
    }
}

// ---------------------------------------------------------------------------
extern "C" void kernel_launch(void* const* d_in, const int* in_sizes, int n_in,
                              void* d_out, int out_size){
    const float* x_in   = (const float*)d_in[0];
    const float* Wq     = (const float*)d_in[1];
    const float* Wk     = (const float*)d_in[2];
    const float* Wv     = (const float*)d_in[3];
    const float* Wo     = (const float*)d_in[4];
    const float* lamb   = (const float*)d_in[5];
    const float* lambdas= (const float*)d_in[6];
    const float* Wfc    = (const float*)d_in[7];
    const float* Wp     = (const float*)d_in[8];
    const int*   levels = (const int*)d_in[9];
    const int*   sidx   = (const int*)d_in[10];
    float* out = (float*)d_out;

    float *px,*px0,*pxl,*pxn,*pq,*pk,*pv,*pv1,*py,*ph,*psc; int* pcpad;
    cudaGetSymbolAddress((void**)&px,  g_x);
    cudaGetSymbolAddress((void**)&px0, g_x0);
    cudaGetSymbolAddress((void**)&pxl, g_xl);
    cudaGetSymbolAddress((void**)&pxn, g_xn);
    cudaGetSymbolAddress((void**)&pq,  g_q);
    cudaGetSymbolAddress((void**)&pk,  g_k);
    cudaGetSymbolAddress((void**)&pv,  g_v);
    cudaGetSymbolAddress((void**)&pv1, g_v1);
    cudaGetSymbolAddress((void**)&py,  g_y);
    cudaGetSymbolAddress((void**)&ph,  g_h);
    cudaGetSymbolAddress((void**)&psc, g_sc);
    cudaGetSymbolAddress((void**)&pcpad, g_cpad);

    const size_t DD  = (size_t)D_ * D_;      // 1M
    const size_t DFD = (size_t)DFF_ * D_;    // 4M

    build_cpad<<<1, 1024>>>(levels, pcpad);
    rms_kernel<<<S_, 256>>>(x_in, px, px0);          // x = rms(x); x0 = x

    for (int i = 0; i < NL_; i++){
        mix_rms_kernel<<<S_, 256>>>(px, px0, lambdas, i, pxl, pxn);

        // fused q/k/v projections: q|k|v = xn @ W^T
        gemm_nt3<<<dim3(8, 8, 3), 256>>>(pxn,
                                         Wq + (size_t)i*DD, Wk + (size_t)i*DD, Wv + (size_t)i*DD,
                                         pq, pk, pv, D_, D_);

        vmix_kernel<<<(S_*D_)/256, 256>>>(pv, pv1, lamb, i, i == 0 ? 1 : 0);

        qk_rmsrope<<<(S_*H_*32)/256, 256>>>(pq, pk);

        attn_scores<<<dim3(16, 16, 16), 256>>>(pq, pk, levels, sidx, pcpad, psc);
        softmax_kernel<<<H_*S_, 256>>>(psc);
        attn_out<<<dim3(16, 16), 256>>>(psc, pv, py);

        // x = xl + y @ Wo^T
        gemm_nt<128,64,8,4,1><<<dim3(16, 8), 256>>>(py, Wo + (size_t)i*DD, pxl, px, D_, D_);

        // MLP
        rms_kernel<<<S_, 256>>>(px, pxn, nullptr);
        gemm_nt<128,128,8,8,2><<<dim3(32, 8), 256>>>(pxn, Wfc + (size_t)i*DFD, nullptr, ph, DFF_, D_);
        gemm_nt<128,64,8,4,1><<<dim3(16, 8), 256>>>(ph, Wp + (size_t)i*DFD, px, px, D_, DFF_);
    }

    rms_kernel<<<S_, 256>>>(px, out, nullptr);
}

// round 9
// speedup vs baseline: 2.3037x; 2.3037x over previous
#include <cuda_runtime.h>
#include <math.h>
#include <stdint.h>

// Problem dims (fixed by the reference)
static constexpr int S_   = 1024;
static constexpr int D_   = 1024;
static constexpr int H_   = 16;
static constexpr int HD_  = 64;
static constexpr int NL_  = 6;
static constexpr int DFF_ = 4096;
static constexpr float EPS_ = 1.1920929e-07f;

// ---------------- scratch (static device globals; no allocations) ----------
__device__ float g_x [S_*D_];
__device__ float g_x0[S_*D_];
__device__ float g_xl[S_*D_];
__device__ float g_xn[S_*D_];
__device__ float g_q [S_*D_];
__device__ float g_k [S_*D_];
__device__ float g_v [S_*D_];
__device__ float g_v1[S_*D_];
__device__ float g_y [S_*D_];
__device__ float g_h [S_*DFF_];
__device__ float g_sc[(size_t)H_*S_*S_];   // 64 MB scores
__device__ int   g_cpad[S_+1];

// =================== small PTX helpers (baseline ISA only) ==================
__device__ __forceinline__ uint32_t s2u(const void* p){
    return (uint32_t)__cvta_generic_to_shared(p);
}
__device__ __forceinline__ void cp_async16(void* smem_dst, const void* gsrc){
    asm volatile("cp.async.cg.shared.global [%0], [%1], 16;"
                 :: "r"(s2u(smem_dst)), "l"(gsrc) : "memory");
}
__device__ __forceinline__ void cp_commit(){
    asm volatile("cp.async.commit_group;" ::: "memory");
}
__device__ __forceinline__ void cp_wait1(){
    asm volatile("cp.async.wait_group 1;" ::: "memory");
}
__device__ __forceinline__ uint32_t f2tf32(float x){
    uint32_t y;
    asm("cvt.rna.tf32.f32 %0, %1;" : "=r"(y) : "f"(x));
    return y;
}
__device__ __forceinline__ void mma_tf32(float c[4], const uint32_t a[4], const uint32_t b[2]){
    asm volatile(
        "mma.sync.aligned.m16n8k8.row.col.f32.tf32.tf32.f32 "
        "{%0,%1,%2,%3}, {%4,%5,%6,%7}, {%8,%9}, {%0,%1,%2,%3};"
        : "+f"(c[0]), "+f"(c[1]), "+f"(c[2]), "+f"(c[3])
        : "r"(a[0]), "r"(a[1]), "r"(a[2]), "r"(a[3]), "r"(b[0]), "r"(b[1]));
}

// ============== tf32 mma.sync NT GEMM: C[M,N] = A[M,K] @ B[N,K]^T ==========
// 256 threads = 8 warps as 4(M) x 2(N). Warp tile (BM/4) x (BN/2).
// mma tiles per warp: MT = BM/64 (m16), NT = BN/16 (n8). BK=16 (2 k-steps).
// EPI: 0 = none, 1 = C = acc + Cadd, 2 = C = relu(acc)^2
template<int BM, int BN, int EPI>
__device__ __forceinline__ void gemm_mma_body(
    const float* __restrict__ A, const float* __restrict__ B,
    const float* __restrict__ Cadd, float* __restrict__ C,
    int N, int K)
{
    constexpr int BK = 16;
    constexpr int RS = BK + 4;          // row stride in floats (bank-conflict-free)
    constexpr int MT = BM / 64;         // m16 tiles per warp
    constexpr int NT = BN / 16;         // n8 tiles per warp
    constexpr int A4 = (BM * BK / 4) / 256;   // float4 loads per thread (A)
    constexpr int B4 = (BN * BK / 4) / 256;   // float4 loads per thread (B)

    __shared__ float As[2][BM * RS];
    __shared__ float Bs[2][BN * RS];

    const int tid  = threadIdx.x;
    const int lane = tid & 31;
    const int warp = tid >> 5;
    const int wm   = warp >> 1;         // 0..3
    const int wn   = warp & 1;          // 0..1
    const int g    = lane >> 2;         // group id 0..7
    const int t    = lane & 3;          // thread-in-group 0..3

    const int bm = blockIdx.y * BM;
    const int bn = blockIdx.x * BN;
    const int NIT = K / BK;

    float acc[MT][NT][4];
#pragma unroll
    for (int i = 0; i < MT; i++)
#pragma unroll
        for (int j = 0; j < NT; j++)
#pragma unroll
            for (int c = 0; c < 4; c++) acc[i][j][c] = 0.f;

    auto load_stage = [&](int st, int k0){
        const float* Ag = A + (size_t)bm * K + k0;
#pragma unroll
        for (int i = 0; i < A4; i++){
            int s = tid + i * 256;
            int r = s >> 2, c4 = (s & 3) << 2;
            cp_async16(&As[st][r * RS + c4], Ag + (size_t)r * K + c4);
        }
        const float* Bg = B + (size_t)bn * K + k0;
#pragma unroll
        for (int i = 0; i < B4; i++){
            int s = tid + i * 256;
            int r = s >> 2, c4 = (s & 3) << 2;
            cp_async16(&Bs[st][r * RS + c4], Bg + (size_t)r * K + c4);
        }
    };

    load_stage(0, 0);        cp_commit();
    load_stage(1, BK);       cp_commit();

    for (int it = 0; it < NIT; ++it){
        const int st = it & 1;
        cp_wait1();
        __syncthreads();

#pragma unroll
        for (int kk = 0; kk < 2; kk++){
            const int kb = kk * 8;
            uint32_t af[MT][4];
#pragma unroll
            for (int mi = 0; mi < MT; mi++){
                const int r0 = wm * (BM / 4) + mi * 16 + g;
                const float* ap = &As[st][r0 * RS + kb + t];
                af[mi][0] = f2tf32(ap[0]);
                af[mi][1] = f2tf32(ap[8 * RS]);
                af[mi][2] = f2tf32(ap[4]);
                af[mi][3] = f2tf32(ap[8 * RS + 4]);
            }
            uint32_t bf[NT][2];
#pragma unroll
            for (int ni = 0; ni < NT; ni++){
                const int n0 = wn * (BN / 2) + ni * 8 + g;
                const float* bp = &Bs[st][n0 * RS + kb + t];
                bf[ni][0] = f2tf32(bp[0]);
                bf[ni][1] = f2tf32(bp[4]);
            }
#pragma unroll
            for (int mi = 0; mi < MT; mi++)
#pragma unroll
                for (int ni = 0; ni < NT; ni++)
                    mma_tf32(acc[mi][ni], af[mi], bf[ni]);
        }

        __syncthreads();
        if (it + 2 < NIT) load_stage(st, (it + 2) * BK);
        cp_commit();   // empty groups at the tail keep wait_group accounting uniform
    }

    // ---------------- epilogue ----------------
#pragma unroll
    for (int mi = 0; mi < MT; mi++){
#pragma unroll
        for (int rr = 0; rr < 2; rr++){           // c0/c1 then c2/c3 (row +8)
            const int m = bm + wm * (BM / 4) + mi * 16 + g + rr * 8;
#pragma unroll
            for (int ni = 0; ni < NT; ni++){
                const int n = bn + wn * (BN / 2) + ni * 8 + t * 2;
                float v0 = acc[mi][ni][rr * 2 + 0];
                float v1 = acc[mi][ni][rr * 2 + 1];
                if (EPI == 1){
                    const float2 a2 = *(const float2*)(Cadd + (size_t)m * N + n);
                    v0 += a2.x; v1 += a2.y;
                }
                if (EPI == 2){
                    v0 = v0 > 0.f ? v0 * v0 : 0.f;
                    v1 = v1 > 0.f ? v1 * v1 : 0.f;
                }
                float2 o; o.x = v0; o.y = v1;
                *(float2*)(C + (size_t)m * N + n) = o;
            }
        }
    }
}

template<int BM, int BN, int EPI>
__global__ void __launch_bounds__(256)
gemm_mma(const float* __restrict__ A, const float* __restrict__ B,
         const float* __restrict__ Cadd, float* __restrict__ C, int N, int K){
    gemm_mma_body<BM, BN, EPI>(A, B, Cadd, C, N, K);
}

// fused Q/K/V projection: blockIdx.z selects weight + output
__global__ void __launch_bounds__(256)
gemm_mma3(const float* __restrict__ A,
          const float* __restrict__ B0, const float* __restrict__ B1, const float* __restrict__ B2,
          float* __restrict__ C0, float* __restrict__ C1, float* __restrict__ C2,
          int N, int K){
    const float* B = (blockIdx.z == 0) ? B0 : (blockIdx.z == 1 ? B1 : B2);
    float*       C = (blockIdx.z == 0) ? C0 : (blockIdx.z == 1 ? C1 : C2);
    gemm_mma_body<128, 64, 0>(A, B, nullptr, C, N, K);
}

// ---------------- mask prefix (cumsum of levels==0) ------------------------
__global__ void build_cpad(const int* __restrict__ levels, int* __restrict__ cpad){
    __shared__ int sbuf[S_];
    int t = threadIdx.x;
    sbuf[t] = (levels[t] == 0) ? 1 : 0;
    __syncthreads();
    for (int off = 1; off < S_; off <<= 1){
        int v = 0;
        if (t >= off) v = sbuf[t - off];
        __syncthreads();
        sbuf[t] += v;
        __syncthreads();
    }
    cpad[t+1] = sbuf[t];
    if (t == 0) cpad[0] = 0;
}

// ---------------- row RMS norm (row = 1024 elems) ---------------------------
__global__ void rms_kernel(const float* __restrict__ in, float* __restrict__ out,
                           float* __restrict__ out2){
    __shared__ float red[256];
    const int row = blockIdx.x;
    const int t = threadIdx.x;
    const float* r = in + (size_t)row * D_;
    float v[4]; float ss = 0.f;
#pragma unroll
    for (int j = 0; j < 4; j++){ v[j] = r[t + j*256]; ss += v[j]*v[j]; }
    red[t] = ss; __syncthreads();
    for (int o = 128; o > 0; o >>= 1){ if (t < o) red[t] += red[t+o]; __syncthreads(); }
    const float sc = rsqrtf(red[0] * (1.f/D_) + EPS_);
    float* o1 = out + (size_t)row * D_;
#pragma unroll
    for (int j = 0; j < 4; j++){
        float w = v[j] * sc;
        o1[t + j*256] = w;
        if (out2) out2[(size_t)row*D_ + t + j*256] = w;
    }
}

// ---------------- xl = l0*x + l1*x0 ; xn = rms(xl) --------------------------
__global__ void mix_rms_kernel(const float* __restrict__ x, const float* __restrict__ x0,
                               const float* __restrict__ lambdas, int layer,
                               float* __restrict__ xl, float* __restrict__ xn){
    __shared__ float red[256];
    const int row = blockIdx.x;
    const int t = threadIdx.x;
    const float l0 = lambdas[2*layer + 0];
    const float l1 = lambdas[2*layer + 1];
    float v[4]; float ss = 0.f;
#pragma unroll
    for (int j = 0; j < 4; j++){
        size_t idx = (size_t)row*D_ + t + j*256;
        float w = l0 * x[idx] + l1 * x0[idx];
        v[j] = w; xl[idx] = w; ss += w*w;
    }
    red[t] = ss; __syncthreads();
    for (int o = 128; o > 0; o >>= 1){ if (t < o) red[t] += red[t+o]; __syncthreads(); }
    const float sc = rsqrtf(red[0] * (1.f/D_) + EPS_);
#pragma unroll
    for (int j = 0; j < 4; j++){
        size_t idx = (size_t)row*D_ + t + j*256;
        xn[idx] = v[j] * sc;
    }
}

// ---------------- value residual mix ---------------------------------------
__global__ void vmix_kernel(float* __restrict__ v, float* __restrict__ v1,
                            const float* __restrict__ lamb, int layer, int first){
    int i = blockIdx.x * 256 + threadIdx.x;
    if (first){
        v1[i] = v[i];                 // layer 0: v1 = v, mix is identity
    } else {
        float l = lamb[layer];
        v[i] = (1.f - l) * v[i] + l * v1[i];
    }
}

// ---------------- per-head RMS + RoPE on q and k ----------------------------
__global__ void qk_rmsrope(float* __restrict__ q, float* __restrict__ k){
    const int gw   = (blockIdx.x * blockDim.x + threadIdx.x) >> 5;  // 0..16383
    const int lane = threadIdx.x & 31;
    const int t = gw >> 4;
    const int h = gw & 15;

    const float inv = expf(-((float)(2*lane) / 64.f) * logf(10000.f));
    const float fr  = (float)t * inv;
    float sn, cs;
    sincosf(fr, &sn, &cs);

    float* bases[2] = { q + (size_t)t*D_ + h*HD_, k + (size_t)t*D_ + h*HD_ };
#pragma unroll
    for (int p = 0; p < 2; p++){
        float* r = bases[p];
        float x1 = r[lane];
        float x2 = r[lane + 32];
        float ss = x1*x1 + x2*x2;
#pragma unroll
        for (int off = 16; off > 0; off >>= 1)
            ss += __shfl_xor_sync(0xffffffffu, ss, off);
        float sc = rsqrtf(ss * (1.f/HD_) + EPS_);
        x1 *= sc; x2 *= sc;
        r[lane]      =  x1*cs + x2*sn;
        r[lane + 32] = -x1*sn + x2*cs;
    }
}

// ---------------- masked scaled scores: S[h][q][k] --------------------------
__global__ void attn_scores(const float* __restrict__ q, const float* __restrict__ k,
                            const int* __restrict__ levels, const int* __restrict__ samp,
                            const int* __restrict__ cpad, float* __restrict__ scores){
    const int h  = blockIdx.z;
    const int qt = blockIdx.y;
    const int kt = blockIdx.x;
    const int tid = threadIdx.x;
    const int tx = tid & 15, ty = tid >> 4;
    float* Sp = scores + ((size_t)h*S_ + qt*64)*S_ + kt*64;

    if (kt > qt){ // fully above diagonal: all masked
#pragma unroll
        for (int i = 0; i < 4; i++)
#pragma unroll
            for (int j = 0; j < 4; j++)
                Sp[(size_t)(ty*4+i)*S_ + tx*4+j] = -1e30f;
        return;
    }

    __shared__ float Qs[64][65];
    __shared__ float Ks[64][65];
    for (int i = tid; i < 64*16; i += 256){
        int r = i >> 4, c = (i & 15) << 2;
        float4 qv = *(const float4*)(q + (size_t)(qt*64 + r)*D_ + h*HD_ + c);
        Qs[r][c+0]=qv.x; Qs[r][c+1]=qv.y; Qs[r][c+2]=qv.z; Qs[r][c+3]=qv.w;
        float4 kv = *(const float4*)(k + (size_t)(kt*64 + r)*D_ + h*HD_ + c);
        Ks[r][c+0]=kv.x; Ks[r][c+1]=kv.y; Ks[r][c+2]=kv.z; Ks[r][c+3]=kv.w;
    }
    __syncthreads();

    float acc[4][4];
#pragma unroll
    for (int i=0;i<4;i++)
#pragma unroll
        for (int j=0;j<4;j++) acc[i][j]=0.f;

#pragma unroll 8
    for (int d = 0; d < 64; d++){
        float ra[4], rb[4];
#pragma unroll
        for (int i = 0; i < 4; i++) ra[i] = Qs[ty*4+i][d];
#pragma unroll
        for (int j = 0; j < 4; j++) rb[j] = Ks[tx*4+j][d];
#pragma unroll
        for (int i = 0; i < 4; i++)
#pragma unroll
            for (int j = 0; j < 4; j++)
                acc[i][j] = fmaf(ra[i], rb[j], acc[i][j]);
    }

    const float scale = 0.125f;  // HD^-0.5
#pragma unroll
    for (int i = 0; i < 4; i++){
        int qq = qt*64 + ty*4 + i;
#pragma unroll
        for (int j = 0; j < 4; j++){
            int kk = kt*64 + tx*4 + j;
            bool ok = (kk <= qq)
                   && (samp[kk] == samp[qq])
                   && !((levels[kk] == 0) && (cpad[qq] - cpad[kk+1] > 0));
            Sp[(size_t)(ty*4+i)*S_ + tx*4+j] = ok ? acc[i][j]*scale : -1e30f;
        }
    }
}

// ---------------- row softmax over K=1024 -----------------------------------
__global__ void softmax_kernel(float* __restrict__ sc){
    __shared__ float red[256];
    const size_t row = blockIdx.x;
    float* p = sc + row * S_;
    const int t = threadIdx.x;
    float v[4];
    float mx = -1e38f;
#pragma unroll
    for (int j = 0; j < 4; j++){ v[j] = p[t + j*256]; mx = fmaxf(mx, v[j]); }
    red[t] = mx; __syncthreads();
    for (int o = 128; o > 0; o >>= 1){ if (t < o) red[t] = fmaxf(red[t], red[t+o]); __syncthreads(); }
    mx = red[0]; __syncthreads();
    float s = 0.f;
#pragma unroll
    for (int j = 0; j < 4; j++){ v[j] = __expf(v[j] - mx); s += v[j]; }
    red[t] = s; __syncthreads();
    for (int o = 128; o > 0; o >>= 1){ if (t < o) red[t] += red[t+o]; __syncthreads(); }
    const float inv = 1.f / red[0];
#pragma unroll
    for (int j = 0; j < 4; j++) p[t + j*256] = v[j] * inv;
}

// ---------------- y[t][h*64+d] = sum_k P[h][t][k] * v[k][h*64+d] ------------
__global__ void attn_out(const float* __restrict__ scores, const float* __restrict__ v,
                         float* __restrict__ y){
    const int h  = blockIdx.y;
    const int qt = blockIdx.x;
    const int tid = threadIdx.x;
    const int tx = tid & 15, ty = tid >> 4;

    __shared__ float Ps[64][17];
    __shared__ float Vs[16][68];

    float acc[4][4];
#pragma unroll
    for (int i=0;i<4;i++)
#pragma unroll
        for (int j=0;j<4;j++) acc[i][j]=0.f;

    const float* Sp = scores + ((size_t)h*S_ + qt*64)*S_;

    for (int k0 = 0; k0 < S_; k0 += 16){
        {
            int r = tid >> 2, c = (tid & 3) << 2;
            float4 pv = *(const float4*)(Sp + (size_t)r*S_ + k0 + c);
            Ps[r][c+0]=pv.x; Ps[r][c+1]=pv.y; Ps[r][c+2]=pv.z; Ps[r][c+3]=pv.w;
        }
        {
            int r = tid >> 4, c = (tid & 15) << 2;
            float4 vv = *(const float4*)(v + (size_t)(k0 + r)*D_ + h*HD_ + c);
            Vs[r][c+0]=vv.x; Vs[r][c+1]=vv.y; Vs[r][c+2]=vv.z; Vs[r][c+3]=vv.w;
        }
        __syncthreads();
#pragma unroll
        for (int kk = 0; kk < 16; kk++){
            float ra[4];
#pragma unroll
            for (int i = 0; i < 4; i++) ra[i] = Ps[ty*4+i][kk];
            const float4* bp = (const float4*)(&Vs[kk][tx*4]);
            float4 b4 = bp[0];
            float rb[4] = { b4.x, b4.y, b4.z, b4.w };
#pragma unroll
            for (int i = 0; i < 4; i++)
#pragma unroll
                for (int j = 0; j < 4; j++)
                    acc[i][j] = fmaf(ra[i], rb[j], acc[i][j]);
        }
        __syncthreads();
    }

#pragma unroll
    for (int i = 0; i < 4; i++){
        int t = qt*64 + ty*4 + i;
#pragma unroll
        for (int j = 0; j < 4; j++)
            y[(size_t)t*D_ + h*HD_ + tx*4 + j] = acc[i][j];
    }
}

// ---------------------------------------------------------------------------
extern "C" void kernel_launch(void* const* d_in, const int* in_sizes, int n_in,
                              void* d_out, int out_size){
    const float* x_in   = (const float*)d_in[0];
    const float* Wq     = (const float*)d_in[1];
    const float* Wk     = (const float*)d_in[2];
    const float* Wv     = (const float*)d_in[3];
    const float* Wo     = (const float*)d_in[4];
    const float* lamb   = (const float*)d_in[5];
    const float* lambdas= (const float*)d_in[6];
    const float* Wfc    = (const float*)d_in[7];
    const float* Wp     = (const float*)d_in[8];
    const int*   levels = (const int*)d_in[9];
    const int*   sidx   = (const int*)d_in[10];
    float* out = (float*)d_out;

    float *px,*px0,*pxl,*pxn,*pq,*pk,*pv,*pv1,*py,*ph,*psc; int* pcpad;
    cudaGetSymbolAddress((void**)&px,  g_x);
    cudaGetSymbolAddress((void**)&px0, g_x0);
    cudaGetSymbolAddress((void**)&pxl, g_xl);
    cudaGetSymbolAddress((void**)&pxn, g_xn);
    cudaGetSymbolAddress((void**)&pq,  g_q);
    cudaGetSymbolAddress((void**)&pk,  g_k);
    cudaGetSymbolAddress((void**)&pv,  g_v);
    cudaGetSymbolAddress((void**)&pv1, g_v1);
    cudaGetSymbolAddress((void**)&py,  g_y);
    cudaGetSymbolAddress((void**)&ph,  g_h);
    cudaGetSymbolAddress((void**)&psc, g_sc);
    cudaGetSymbolAddress((void**)&pcpad, g_cpad);

    const size_t DD  = (size_t)D_ * D_;      // 1M
    const size_t DFD = (size_t)DFF_ * D_;    // 4M

    build_cpad<<<1, 1024>>>(levels, pcpad);
    rms_kernel<<<S_, 256>>>(x_in, px, px0);          // x = rms(x); x0 = x

    for (int i = 0; i < NL_; i++){
        mix_rms_kernel<<<S_, 256>>>(px, px0, lambdas, i, pxl, pxn);

        // fused q/k/v projections (tf32 mma.sync): q|k|v = xn @ W^T
        gemm_mma3<<<dim3(D_/64, S_/128, 3), 256>>>(
            pxn, Wq + (size_t)i*DD, Wk + (size_t)i*DD, Wv + (size_t)i*DD,
            pq, pk, pv, D_, D_);

        vmix_kernel<<<(S_*D_)/256, 256>>>(pv, pv1, lamb, i, i == 0 ? 1 : 0);

        qk_rmsrope<<<(S_*H_*32)/256, 256>>>(pq, pk);

        attn_scores<<<dim3(16, 16, 16), 256>>>(pq, pk, levels, sidx, pcpad, psc);
        softmax_kernel<<<H_*S_, 256>>>(psc);
        attn_out<<<dim3(16, 16), 256>>>(psc, pv, py);

        // x = xl + y @ Wo^T
        gemm_mma<128,64,1><<<dim3(D_/64, S_/128), 256>>>(
            py, Wo + (size_t)i*DD, pxl, px, D_, D_);

        // MLP
        rms_kernel<<<S_, 256>>>(px, pxn, nullptr);
        gemm_mma<128,128,2><<<dim3(DFF_/128, S_/128), 256>>>(
            pxn, Wfc + (size_t)i*DFD, nullptr, ph, DFF_, D_);
        gemm_mma<128,64,1><<<dim3(D_/64, S_/128), 256>>>(
            ph, Wp + (size_t)i*DFD, px, px, D_, DFF_);
    }

    rms_kernel<<<S_, 256>>>(px, out, nullptr);
}

// round 10
// speedup vs baseline: 2.4832x; 1.0779x over previous
#include <cuda_runtime.h>
#include <math.h>
#include <stdint.h>

// Problem dims (fixed by the reference)
static constexpr int S_   = 1024;
static constexpr int D_   = 1024;
static constexpr int H_   = 16;
static constexpr int HD_  = 64;
static constexpr int NL_  = 6;
static constexpr int DFF_ = 4096;
static constexpr float EPS_ = 1.1920929e-07f;

static constexpr size_t DD_  = (size_t)D_ * D_;        // 1M
static constexpr size_t DFD_ = (size_t)DFF_ * D_;      // 4M
static constexpr size_t WQKVO_ = (size_t)NL_ * DD_;    // 6.29M floats each
static constexpr size_t WFF_   = (size_t)NL_ * DFD_;   // 25.2M floats each

// ---------------- scratch (static device globals; no allocations) ----------
__device__ float g_x [S_*D_];
__device__ float g_x0[S_*D_];
__device__ float g_xl[S_*D_];
__device__ float g_xn[S_*D_];
__device__ float g_q [S_*D_];
__device__ float g_k [S_*D_];
__device__ float g_v [S_*D_];
__device__ float g_v1[S_*D_];
__device__ float g_y [S_*D_];
__device__ float g_h [S_*DFF_];
__device__ float g_sc[(size_t)H_*S_*S_];   // 64 MB scores/probs
__device__ int   g_cpad[S_+1];
__device__ float g_w[4*WQKVO_ + 2*WFF_];   // tf32-rounded weight mirror (~302 MB)

// =================== small PTX helpers (baseline ISA only) ==================
__device__ __forceinline__ uint32_t s2u(const void* p){
    return (uint32_t)__cvta_generic_to_shared(p);
}
__device__ __forceinline__ void cp_async16(void* smem_dst, const void* gsrc){
    asm volatile("cp.async.cg.shared.global [%0], [%1], 16;"
                 :: "r"(s2u(smem_dst)), "l"(gsrc) : "memory");
}
__device__ __forceinline__ void cp_commit(){
    asm volatile("cp.async.commit_group;" ::: "memory");
}
__device__ __forceinline__ void cp_wait1(){
    asm volatile("cp.async.wait_group 1;" ::: "memory");
}
__device__ __forceinline__ uint32_t f2tf32(float x){
    uint32_t y;
    asm("cvt.rna.tf32.f32 %0, %1;" : "=r"(y) : "f"(x));
    return y;
}
__device__ __forceinline__ float roundtf(float x){
    return __uint_as_float(f2tf32(x));
}
__device__ __forceinline__ void mma_tf32(float c[4], const uint32_t a[4], const uint32_t b[2]){
    asm volatile(
        "mma.sync.aligned.m16n8k8.row.col.f32.tf32.tf32.f32 "
        "{%0,%1,%2,%3}, {%4,%5,%6,%7}, {%8,%9}, {%0,%1,%2,%3};"
        : "+f"(c[0]), "+f"(c[1]), "+f"(c[2]), "+f"(c[3])
        : "r"(a[0]), "r"(a[1]), "r"(a[2]), "r"(a[3]), "r"(b[0]), "r"(b[1]));
}

// ---------------- weight pre-round (fp32 -> tf32-bit-pattern fp32) ----------
__global__ void __launch_bounds__(256)
round_w(const float4* __restrict__ src, float4* __restrict__ dst, int n4){
    int i = blockIdx.x * 256 + threadIdx.x;
    const int stride = gridDim.x * 256;
    for (; i < n4; i += stride){
        float4 a = src[i];
        a.x = roundtf(a.x); a.y = roundtf(a.y);
        a.z = roundtf(a.z); a.w = roundtf(a.w);
        dst[i] = a;
    }
}

// ============== tf32 mma.sync NT GEMM: C[M,N] = A[M,K] @ B[N,K]^T ==========
// Operands must already be tf32-rounded bit patterns (no cvt in the loop).
// 256 threads = 8 warps as 4(M) x 2(N). EPI: 0=none, 1=+Cadd, 2=relu^2(+round)
template<int BM, int BN, int EPI>
__device__ __forceinline__ void gemm_mma_body(
    const float* __restrict__ A, const float* __restrict__ B,
    const float* __restrict__ Cadd, float* __restrict__ C,
    int N, int K)
{
    constexpr int BK = 16;
    constexpr int RS = BK + 4;
    constexpr int MT = BM / 64;
    constexpr int NT = BN / 16;
    constexpr int A4 = (BM * BK / 4) / 256;
    constexpr int B4 = (BN * BK / 4) / 256;

    __shared__ float As[2][BM * RS];
    __shared__ float Bs[2][BN * RS];

    const int tid  = threadIdx.x;
    const int lane = tid & 31;
    const int warp = tid >> 5;
    const int wm   = warp >> 1;
    const int wn   = warp & 1;
    const int g    = lane >> 2;
    const int t    = lane & 3;

    const int bm = blockIdx.y * BM;
    const int bn = blockIdx.x * BN;
    const int NIT = K / BK;

    float acc[MT][NT][4];
#pragma unroll
    for (int i = 0; i < MT; i++)
#pragma unroll
        for (int j = 0; j < NT; j++)
#pragma unroll
            for (int c = 0; c < 4; c++) acc[i][j][c] = 0.f;

    auto load_stage = [&](int st, int k0){
        const float* Ag = A + (size_t)bm * K + k0;
#pragma unroll
        for (int i = 0; i < A4; i++){
            int s = tid + i * 256;
            int r = s >> 2, c4 = (s & 3) << 2;
            cp_async16(&As[st][r * RS + c4], Ag + (size_t)r * K + c4);
        }
        const float* Bg = B + (size_t)bn * K + k0;
#pragma unroll
        for (int i = 0; i < B4; i++){
            int s = tid + i * 256;
            int r = s >> 2, c4 = (s & 3) << 2;
            cp_async16(&Bs[st][r * RS + c4], Bg + (size_t)r * K + c4);
        }
    };

    load_stage(0, 0);        cp_commit();
    load_stage(1, BK);       cp_commit();

    for (int it = 0; it < NIT; ++it){
        const int st = it & 1;
        cp_wait1();
        __syncthreads();

#pragma unroll
        for (int kk = 0; kk < 2; kk++){
            const int kb = kk * 8;
            uint32_t af[MT][4];
#pragma unroll
            for (int mi = 0; mi < MT; mi++){
                const int r0 = wm * (BM / 4) + mi * 16 + g;
                const float* ap = &As[st][r0 * RS + kb + t];
                af[mi][0] = __float_as_uint(ap[0]);
                af[mi][1] = __float_as_uint(ap[8 * RS]);
                af[mi][2] = __float_as_uint(ap[4]);
                af[mi][3] = __float_as_uint(ap[8 * RS + 4]);
            }
            uint32_t bf[NT][2];
#pragma unroll
            for (int ni = 0; ni < NT; ni++){
                const int n0 = wn * (BN / 2) + ni * 8 + g;
                const float* bp = &Bs[st][n0 * RS + kb + t];
                bf[ni][0] = __float_as_uint(bp[0]);
                bf[ni][1] = __float_as_uint(bp[4]);
            }
#pragma unroll
            for (int mi = 0; mi < MT; mi++)
#pragma unroll
                for (int ni = 0; ni < NT; ni++)
                    mma_tf32(acc[mi][ni], af[mi], bf[ni]);
        }

        __syncthreads();
        if (it + 2 < NIT) load_stage(st, (it + 2) * BK);
        cp_commit();
    }

#pragma unroll
    for (int mi = 0; mi < MT; mi++){
#pragma unroll
        for (int rr = 0; rr < 2; rr++){
            const int m = bm + wm * (BM / 4) + mi * 16 + g + rr * 8;
#pragma unroll
            for (int ni = 0; ni < NT; ni++){
                const int n = bn + wn * (BN / 2) + ni * 8 + t * 2;
                float v0 = acc[mi][ni][rr * 2 + 0];
                float v1 = acc[mi][ni][rr * 2 + 1];
                if (EPI == 1){
                    const float2 a2 = *(const float2*)(Cadd + (size_t)m * N + n);
                    v0 += a2.x; v1 += a2.y;
                }
                if (EPI == 2){
                    v0 = v0 > 0.f ? v0 * v0 : 0.f;
                    v1 = v1 > 0.f ? v1 * v1 : 0.f;
                    v0 = roundtf(v0); v1 = roundtf(v1);   // feeds next GEMM
                }
                float2 o; o.x = v0; o.y = v1;
                *(float2*)(C + (size_t)m * N + n) = o;
            }
        }
    }
}

template<int BM, int BN, int EPI>
__global__ void __launch_bounds__(256)
gemm_mma(const float* __restrict__ A, const float* __restrict__ B,
         const float* __restrict__ Cadd, float* __restrict__ C, int N, int K){
    gemm_mma_body<BM, BN, EPI>(A, B, Cadd, C, N, K);
}

__global__ void __launch_bounds__(256)
gemm_mma3(const float* __restrict__ A,
          const float* __restrict__ B0, const float* __restrict__ B1, const float* __restrict__ B2,
          float* __restrict__ C0, float* __restrict__ C1, float* __restrict__ C2,
          int N, int K){
    const float* B = (blockIdx.z == 0) ? B0 : (blockIdx.z == 1 ? B1 : B2);
    float*       C = (blockIdx.z == 0) ? C0 : (blockIdx.z == 1 ? C1 : C2);
    gemm_mma_body<128, 64, 0>(A, B, nullptr, C, N, K);
}

// ---------------- mask prefix (cumsum of levels==0) ------------------------
__global__ void build_cpad(const int* __restrict__ levels, int* __restrict__ cpad){
    __shared__ int sbuf[S_];
    int t = threadIdx.x;
    sbuf[t] = (levels[t] == 0) ? 1 : 0;
    __syncthreads();
    for (int off = 1; off < S_; off <<= 1){
        int v = 0;
        if (t >= off) v = sbuf[t - off];
        __syncthreads();
        sbuf[t] += v;
        __syncthreads();
    }
    cpad[t+1] = sbuf[t];
    if (t == 0) cpad[0] = 0;
}

// ---------------- row RMS norm (ROUND: tf32-round the output) ---------------
template<int ROUND>
__global__ void rms_kernel(const float* __restrict__ in, float* __restrict__ out,
                           float* __restrict__ out2){
    __shared__ float red[256];
    const int row = blockIdx.x;
    const int t = threadIdx.x;
    const float* r = in + (size_t)row * D_;
    float v[4]; float ss = 0.f;
#pragma unroll
    for (int j = 0; j < 4; j++){ v[j] = r[t + j*256]; ss += v[j]*v[j]; }
    red[t] = ss; __syncthreads();
    for (int o = 128; o > 0; o >>= 1){ if (t < o) red[t] += red[t+o]; __syncthreads(); }
    const float sc = rsqrtf(red[0] * (1.f/D_) + EPS_);
    float* o1 = out + (size_t)row * D_;
#pragma unroll
    for (int j = 0; j < 4; j++){
        float w = v[j] * sc;
        o1[t + j*256] = ROUND ? roundtf(w) : w;
        if (out2) out2[(size_t)row*D_ + t + j*256] = w;
    }
}

// ---------------- xl = l0*x + l1*x0 ; xn = round(rms(xl)) -------------------
__global__ void mix_rms_kernel(const float* __restrict__ x, const float* __restrict__ x0,
                               const float* __restrict__ lambdas, int layer,
                               float* __restrict__ xl, float* __restrict__ xn){
    __shared__ float red[256];
    const int row = blockIdx.x;
    const int t = threadIdx.x;
    const float l0 = lambdas[2*layer + 0];
    const float l1 = lambdas[2*layer + 1];
    float v[4]; float ss = 0.f;
#pragma unroll
    for (int j = 0; j < 4; j++){
        size_t idx = (size_t)row*D_ + t + j*256;
        float w = l0 * x[idx] + l1 * x0[idx];
        v[j] = w; xl[idx] = w; ss += w*w;
    }
    red[t] = ss; __syncthreads();
    for (int o = 128; o > 0; o >>= 1){ if (t < o) red[t] += red[t+o]; __syncthreads(); }
    const float sc = rsqrtf(red[0] * (1.f/D_) + EPS_);
#pragma unroll
    for (int j = 0; j < 4; j++){
        size_t idx = (size_t)row*D_ + t + j*256;
        xn[idx] = roundtf(v[j] * sc);
    }
}

// ---------------- value residual mix (rounds v for the P@V mma) -------------
__global__ void vmix_kernel(float* __restrict__ v, float* __restrict__ v1,
                            const float* __restrict__ lamb, int layer, int first){
    int i = blockIdx.x * 256 + threadIdx.x;
    if (first){
        float w = roundtf(v[i]);
        v[i] = w; v1[i] = w;
    } else {
        float l = lamb[layer];
        v[i] = roundtf((1.f - l) * v[i] + l * v1[i]);
    }
}

// ---------------- per-head RMS + RoPE on q and k (rounds outputs) -----------
__global__ void qk_rmsrope(float* __restrict__ q, float* __restrict__ k){
    const int gw   = (blockIdx.x * blockDim.x + threadIdx.x) >> 5;
    const int lane = threadIdx.x & 31;
    const int t = gw >> 4;
    const int h = gw & 15;

    const float inv = expf(-((float)(2*lane) / 64.f) * logf(10000.f));
    const float fr  = (float)t * inv;
    float sn, cs;
    sincosf(fr, &sn, &cs);

    float* bases[2] = { q + (size_t)t*D_ + h*HD_, k + (size_t)t*D_ + h*HD_ };
#pragma unroll
    for (int p = 0; p < 2; p++){
        float* r = bases[p];
        float x1 = r[lane];
        float x2 = r[lane + 32];
        float ss = x1*x1 + x2*x2;
#pragma unroll
        for (int off = 16; off > 0; off >>= 1)
            ss += __shfl_xor_sync(0xffffffffu, ss, off);
        float sc = rsqrtf(ss * (1.f/HD_) + EPS_);
        x1 *= sc; x2 *= sc;
        r[lane]      = roundtf( x1*cs + x2*sn);
        r[lane + 32] = roundtf(-x1*sn + x2*cs);
    }
}

// ---------------- masked scores via tf32 mma: S[h][q][k] --------------------
// 128 threads = 4 warps; warp w: rows w*16..w*16+15 of a 64x64 tile.
__global__ void __launch_bounds__(128)
attn_scores_mma(const float* __restrict__ q, const float* __restrict__ k,
                const int* __restrict__ levels, const int* __restrict__ samp,
                const int* __restrict__ cpad, float* __restrict__ scores){
    const int h = blockIdx.z, qt = blockIdx.y, kt = blockIdx.x;
    if (kt > qt) return;                    // upper tiles never read downstream

    __shared__ float Qs[64][68];
    __shared__ float Ks[64][68];
    __shared__ int sq[64], cq[64], sk[64], ck1[64];
    __shared__ int lk0[64];

    const int tid = threadIdx.x;
    for (int i = tid; i < 1024; i += 128){
        int r = i >> 4, c = (i & 15) << 2;
        *(float4*)&Qs[r][c] = *(const float4*)(q + (size_t)(qt*64 + r)*D_ + h*HD_ + c);
        *(float4*)&Ks[r][c] = *(const float4*)(k + (size_t)(kt*64 + r)*D_ + h*HD_ + c);
    }
    if (tid < 64){
        int qq = qt*64 + tid, kk = kt*64 + tid;
        sq[tid] = samp[qq]; cq[tid] = cpad[qq];
        sk[tid] = samp[kk]; ck1[tid] = cpad[kk+1];
        lk0[tid] = (levels[kk] == 0);
    }
    __syncthreads();

    const int warp = tid >> 5, lane = tid & 31;
    const int g = lane >> 2, t = lane & 3;
    const int r0 = warp*16 + g;

    float acc[8][4];
#pragma unroll
    for (int i = 0; i < 8; i++)
#pragma unroll
        for (int c = 0; c < 4; c++) acc[i][c] = 0.f;

#pragma unroll
    for (int ks = 0; ks < 8; ks++){
        const int kb = ks*8;
        uint32_t A[4] = {
            __float_as_uint(Qs[r0    ][kb+t  ]),
            __float_as_uint(Qs[r0 + 8][kb+t  ]),
            __float_as_uint(Qs[r0    ][kb+t+4]),
            __float_as_uint(Qs[r0 + 8][kb+t+4]) };
#pragma unroll
        for (int ni = 0; ni < 8; ni++){
            uint32_t B[2] = {
                __float_as_uint(Ks[ni*8+g][kb+t  ]),
                __float_as_uint(Ks[ni*8+g][kb+t+4]) };
            mma_tf32(acc[ni], A, B);
        }
    }

    float* Sp = scores + ((size_t)h*S_ + qt*64)*(size_t)S_ + kt*64;
#pragma unroll
    for (int ni = 0; ni < 8; ni++){
#pragma unroll
        for (int rr = 0; rr < 2; rr++){
            const int m = warp*16 + g + rr*8;
            const int n0 = ni*8 + t*2;
            const int qq = qt*64 + m;
            float2 o;
#pragma unroll
            for (int cc = 0; cc < 2; cc++){
                const int n = n0 + cc;
                const int kk = kt*64 + n;
                bool ok = (kk <= qq) && (sk[n] == sq[m])
                       && !(lk0[n] && (cq[m] - ck1[n] > 0));
                float val = ok ? acc[ni][rr*2+cc] * 0.125f : -1e30f;
                (cc ? o.y : o.x) = val;
            }
            *(float2*)(Sp + (size_t)m*S_ + n0) = o;
        }
    }
}

// ---------------- row softmax over causal prefix only; rounds P -------------
__global__ void softmax_kernel(float* __restrict__ sc){
    __shared__ float red[256];
    const int row = blockIdx.x;                 // h*S + q
    const int qpos = row & (S_-1);
    const int kmax = ((qpos >> 6) + 1) << 6;
    float* p = sc + (size_t)row * S_;
    const int t = threadIdx.x;
    float v[4];
    float mx = -1e38f;
#pragma unroll
    for (int j = 0; j < 4; j++){
        int idx = t + j*256;
        v[j] = (idx < kmax) ? p[idx] : -1e38f;
        mx = fmaxf(mx, v[j]);
    }
    red[t] = mx; __syncthreads();
    for (int o = 128; o > 0; o >>= 1){ if (t < o) red[t] = fmaxf(red[t], red[t+o]); __syncthreads(); }
    mx = red[0]; __syncthreads();
    float s = 0.f;
#pragma unroll
    for (int j = 0; j < 4; j++){
        int idx = t + j*256;
        v[j] = (idx < kmax) ? __expf(v[j] - mx) : 0.f;
        s += v[j];
    }
    red[t] = s; __syncthreads();
    for (int o = 128; o > 0; o >>= 1){ if (t < o) red[t] += red[t+o]; __syncthreads(); }
    const float inv = 1.f / red[0];
#pragma unroll
    for (int j = 0; j < 4; j++){
        int idx = t + j*256;
        if (idx < kmax) p[idx] = roundtf(v[j] * inv);
    }
}

// ---------------- y = P @ V via tf32 mma (causal K range only) --------------
// 128 threads = 4 warps; CTA computes a 64(q) x 64(d) tile for one head.
__global__ void __launch_bounds__(128)
attn_pv(const float* __restrict__ P, const float* __restrict__ v, float* __restrict__ y){
    const int h = blockIdx.y, qt = blockIdx.x;
    __shared__ float Ps[64][36];
    __shared__ float Vt[64][35];        // [n(dim)][k(token)] transposed

    const int tid = threadIdx.x;
    const int warp = tid >> 5, lane = tid & 31;
    const int g = lane >> 2, t = lane & 3;
    const int r0 = warp*16 + g;
    const float* Pp = P + ((size_t)h*S_ + qt*64)*(size_t)S_;
    const int kmax = (qt + 1) * 64;

    float acc[8][4];
#pragma unroll
    for (int i = 0; i < 8; i++)
#pragma unroll
        for (int c = 0; c < 4; c++) acc[i][c] = 0.f;

    for (int k0 = 0; k0 < kmax; k0 += 32){
        for (int i = tid; i < 512; i += 128){
            int r = i >> 3, c = (i & 7) << 2;
            *(float4*)&Ps[r][c] = *(const float4*)(Pp + (size_t)r*S_ + k0 + c);
        }
        for (int i = tid; i < 512; i += 128){
            int kk = i >> 4, c = (i & 15) << 2;
            float4 vv = *(const float4*)(v + (size_t)(k0+kk)*D_ + h*HD_ + c);
            Vt[c+0][kk] = vv.x; Vt[c+1][kk] = vv.y;
            Vt[c+2][kk] = vv.z; Vt[c+3][kk] = vv.w;
        }
        __syncthreads();

#pragma unroll
        for (int ks = 0; ks < 4; ks++){
            const int kb = ks*8;
            uint32_t A[4] = {
                __float_as_uint(Ps[r0    ][kb+t  ]),
                __float_as_uint(Ps[r0 + 8][kb+t  ]),
                __float_as_uint(Ps[r0    ][kb+t+4]),
                __float_as_uint(Ps[r0 + 8][kb+t+4]) };
#pragma unroll
            for (int ni = 0; ni < 8; ni++){
                uint32_t B[2] = {
                    __float_as_uint(Vt[ni*8+g][kb+t  ]),
                    __float_as_uint(Vt[ni*8+g][kb+t+4]) };
                mma_tf32(acc[ni], A, B);
            }
        }
        __syncthreads();
    }

#pragma unroll
    for (int ni = 0; ni < 8; ni++){
#pragma unroll
        for (int rr = 0; rr < 2; rr++){
            const int m = warp*16 + g + rr*8;
            const int n0 = ni*8 + t*2;
            float2 o;
            o.x = roundtf(acc[ni][rr*2+0]);     // y feeds the Wo GEMM
            o.y = roundtf(acc[ni][rr*2+1]);
            *(float2*)(y + (size_t)(qt*64 + m)*D_ + h*HD_ + n0) = o;
        }
    }
}

// ---------------------------------------------------------------------------
extern "C" void kernel_launch(void* const* d_in, const int* in_sizes, int n_in,
                              void* d_out, int out_size){
    const float* x_in   = (const float*)d_in[0];
    const float* Wq     = (const float*)d_in[1];
    const float* Wk     = (const float*)d_in[2];
    const float* Wv     = (const float*)d_in[3];
    const float* Wo     = (const float*)d_in[4];
    const float* lamb   = (const float*)d_in[5];
    const float* lambdas= (const float*)d_in[6];
    const float* Wfc    = (const float*)d_in[7];
    const float* Wp     = (const float*)d_in[8];
    const int*   levels = (const int*)d_in[9];
    const int*   sidx   = (const int*)d_in[10];
    float* out = (float*)d_out;

    float *px,*px0,*pxl,*pxn,*pq,*pk,*pv,*pv1,*py,*ph,*psc,*pw; int* pcpad;
    cudaGetSymbolAddress((void**)&px,  g_x);
    cudaGetSymbolAddress((void**)&px0, g_x0);
    cudaGetSymbolAddress((void**)&pxl, g_xl);
    cudaGetSymbolAddress((void**)&pxn, g_xn);
    cudaGetSymbolAddress((void**)&pq,  g_q);
    cudaGetSymbolAddress((void**)&pk,  g_k);
    cudaGetSymbolAddress((void**)&pv,  g_v);
    cudaGetSymbolAddress((void**)&pv1, g_v1);
    cudaGetSymbolAddress((void**)&py,  g_y);
    cudaGetSymbolAddress((void**)&ph,  g_h);
    cudaGetSymbolAddress((void**)&psc, g_sc);
    cudaGetSymbolAddress((void**)&pw,  g_w);
    cudaGetSymbolAddress((void**)&pcpad, g_cpad);

    float* rwq = pw;
    float* rwk = pw + WQKVO_;
    float* rwv = pw + 2*WQKVO_;
    float* rwo = pw + 3*WQKVO_;
    float* rwfc= pw + 4*WQKVO_;
    float* rwp = pw + 4*WQKVO_ + WFF_;

    // per-call weight pre-round into tf32 bit patterns
    round_w<<<592, 256>>>((const float4*)Wq,  (float4*)rwq,  (int)(WQKVO_/4));
    round_w<<<592, 256>>>((const float4*)Wk,  (float4*)rwk,  (int)(WQKVO_/4));
    round_w<<<592, 256>>>((const float4*)Wv,  (float4*)rwv,  (int)(WQKVO_/4));
    round_w<<<592, 256>>>((const float4*)Wo,  (float4*)rwo,  (int)(WQKVO_/4));
    round_w<<<592, 256>>>((const float4*)Wfc, (float4*)rwfc, (int)(WFF_/4));
    round_w<<<592, 256>>>((const float4*)Wp,  (float4*)rwp,  (int)(WFF_/4));

    build_cpad<<<1, 1024>>>(levels, pcpad);
    rms_kernel<0><<<S_, 256>>>(x_in, px, px0);        // x = rms(x); x0 = x

    for (int i = 0; i < NL_; i++){
        mix_rms_kernel<<<S_, 256>>>(px, px0, lambdas, i, pxl, pxn);

        gemm_mma3<<<dim3(D_/64, S_/128, 3), 256>>>(
            pxn, rwq + i*DD_, rwk + i*DD_, rwv + i*DD_,
            pq, pk, pv, D_, D_);

        vmix_kernel<<<(S_*D_)/256, 256>>>(pv, pv1, lamb, i, i == 0 ? 1 : 0);
        qk_rmsrope<<<(S_*H_*32)/256, 256>>>(pq, pk);

        attn_scores_mma<<<dim3(16, 16, 16), 128>>>(pq, pk, levels, sidx, pcpad, psc);
        softmax_kernel<<<H_*S_, 256>>>(psc);
        attn_pv<<<dim3(16, 16), 128>>>(psc, pv, py);

        gemm_mma<128,64,1><<<dim3(D_/64, S_/128), 256>>>(
            py, rwo + i*DD_, pxl, px, D_, D_);

        rms_kernel<1><<<S_, 256>>>(px, pxn, nullptr);
        gemm_mma<128,128,2><<<dim3(DFF_/128, S_/128), 256>>>(
            pxn, rwfc + i*DFD_, nullptr, ph, DFF_, D_);
        gemm_mma<128,64,1><<<dim3(D_/64, S_/128), 256>>>(
            ph, rwp + i*DFD_, px, px, D_, DFF_);
    }

    rms_kernel<0><<<S_, 256>>>(px, out, nullptr);
}

// round 12
// speedup vs baseline: 2.4903x; 1.0029x over previous
#include <cuda_runtime.h>
#include <math.h>
#include <stdint.h>

// Problem dims (fixed by the reference)
static constexpr int S_   = 1024;
static constexpr int D_   = 1024;
static constexpr int H_   = 16;
static constexpr int HD_  = 64;
static constexpr int NL_  = 6;
static constexpr int DFF_ = 4096;
static constexpr float EPS_ = 1.1920929e-07f;

static constexpr size_t DD_  = (size_t)D_ * D_;        // 1M
static constexpr size_t DFD_ = (size_t)DFF_ * D_;      // 4M

// ---------------- scratch (static device globals; no allocations) ----------
__device__ float g_x [S_*D_];
__device__ float g_x0[S_*D_];
__device__ float g_xl[S_*D_];
__device__ float g_xn[S_*D_];
__device__ float g_q [S_*D_];
__device__ float g_k [S_*D_];
__device__ float g_v [S_*D_];
__device__ float g_v1[S_*D_];
__device__ float g_y [S_*D_];
__device__ float g_h [S_*DFF_];
__device__ float g_sc[(size_t)H_*S_*S_];   // 64 MB scores/probs
__device__ int   g_cpad[S_+1];

// =================== small PTX helpers (baseline ISA only) ==================
__device__ __forceinline__ uint32_t s2u(const void* p){
    return (uint32_t)__cvta_generic_to_shared(p);
}
__device__ __forceinline__ void cp_async16(void* smem_dst, const void* gsrc){
    asm volatile("cp.async.cg.shared.global [%0], [%1], 16;"
                 :: "r"(s2u(smem_dst)), "l"(gsrc) : "memory");
}
__device__ __forceinline__ void cp_commit(){
    asm volatile("cp.async.commit_group;" ::: "memory");
}
__device__ __forceinline__ void cp_wait1(){
    asm volatile("cp.async.wait_group 1;" ::: "memory");
}
__device__ __forceinline__ uint32_t f2tf32(float x){
    uint32_t y;
    asm("cvt.rna.tf32.f32 %0, %1;" : "=r"(y) : "f"(x));
    return y;
}
__device__ __forceinline__ float roundtf(float x){
    return __uint_as_float(f2tf32(x));
}
__device__ __forceinline__ void mma_tf32(float c[4], const uint32_t a[4], const uint32_t b[2]){
    asm volatile(
        "mma.sync.aligned.m16n8k8.row.col.f32.tf32.tf32.f32 "
        "{%0,%1,%2,%3}, {%4,%5,%6,%7}, {%8,%9}, {%0,%1,%2,%3};"
        : "+f"(c[0]), "+f"(c[1]), "+f"(c[2]), "+f"(c[3])
        : "r"(a[0]), "r"(a[1]), "r"(a[2]), "r"(a[3]), "r"(b[0]), "r"(b[1]));
}

// ============== tf32 mma.sync NT GEMM: C[M,N] = A[M,K] @ B[N,K]^T ==========
// 128 threads = 4 warps as 2(M) x 2(N); warp tile 64x32 -> MT=4 (m16), NT=4 (n8).
// A must be tf32-rounded already; B (weights) is cvt'ed at fragment load.
// EPI: 0=none, 1=C=acc+Cadd, 2=C=round(relu(acc)^2)
// EPI 10: QKV fused variant handled by wrapper (raw write or vmix, see below).
template<int BM, int BN>
struct GemmAcc { float a[ (BM/32) * (BN/16) ][4]; };

template<int BM, int BN, int EPI>
__device__ __forceinline__ void gemm_mma_body(
    const float* __restrict__ A, const float* __restrict__ B,
    const float* __restrict__ Cadd, float* __restrict__ C,
    int N, int K,
    // fused V-mix extras (used only when EPI==3)
    float* __restrict__ Vone, float lamVal, int first)
{
    constexpr int BK = 16;
    constexpr int RS = BK + 4;               // 20 floats; 16B-aligned rows
    constexpr int MT = BM / 32;              // 4  (warp M = BM/2, /16)
    constexpr int NT = BN / 16;              // 4  (warp N = BN/2, /8)
    constexpr int A4 = (BM * BK / 4) / 128;  // float4 per thread (A): 4
    constexpr int B4 = (BN * BK / 4) / 128;  // float4 per thread (B): 2

    __shared__ float As[2][BM * RS];
    __shared__ float Bs[2][BN * RS];

    const int tid  = threadIdx.x;
    const int lane = tid & 31;
    const int warp = tid >> 5;
    const int wm   = warp >> 1;              // 0..1
    const int wn   = warp & 1;               // 0..1
    const int g    = lane >> 2;              // 0..7
    const int t    = lane & 3;               // 0..3

    const int bm = blockIdx.y * BM;
    const int bn = blockIdx.x * BN;
    const int NIT = K / BK;

    float acc[MT][NT][4];
#pragma unroll
    for (int i = 0; i < MT; i++)
#pragma unroll
        for (int j = 0; j < NT; j++)
#pragma unroll
            for (int c = 0; c < 4; c++) acc[i][j][c] = 0.f;

    auto load_stage = [&](int st, int k0){
        const float* Ag = A + (size_t)bm * K + k0;
#pragma unroll
        for (int i = 0; i < A4; i++){
            int s = tid + i * 128;
            int r = s >> 2, c4 = (s & 3) << 2;
            cp_async16(&As[st][r * RS + c4], Ag + (size_t)r * K + c4);
        }
        const float* Bg = B + (size_t)bn * K + k0;
#pragma unroll
        for (int i = 0; i < B4; i++){
            int s = tid + i * 128;
            int r = s >> 2, c4 = (s & 3) << 2;
            cp_async16(&Bs[st][r * RS + c4], Bg + (size_t)r * K + c4);
        }
    };

    load_stage(0, 0);        cp_commit();
    load_stage(1, BK);       cp_commit();

    for (int it = 0; it < NIT; ++it){
        const int st = it & 1;
        cp_wait1();
        __syncthreads();

#pragma unroll
        for (int kk = 0; kk < 2; kk++){
            const int kb = kk * 8;
            uint32_t af[MT][4];
#pragma unroll
            for (int mi = 0; mi < MT; mi++){
                const int r0 = wm * (BM/2) + mi * 16 + g;
                const float* ap = &As[st][r0 * RS + kb + t];
                af[mi][0] = __float_as_uint(ap[0]);
                af[mi][1] = __float_as_uint(ap[8 * RS]);
                af[mi][2] = __float_as_uint(ap[4]);
                af[mi][3] = __float_as_uint(ap[8 * RS + 4]);
            }
            uint32_t bf[NT][2];
#pragma unroll
            for (int ni = 0; ni < NT; ni++){
                const int n0 = wn * (BN/2) + ni * 8 + g;
                const float* bp = &Bs[st][n0 * RS + kb + t];
                bf[ni][0] = f2tf32(bp[0]);       // weights cvt'ed here (B side only)
                bf[ni][1] = f2tf32(bp[4]);
            }
#pragma unroll
            for (int mi = 0; mi < MT; mi++)
#pragma unroll
                for (int ni = 0; ni < NT; ni++)
                    mma_tf32(acc[mi][ni], af[mi], bf[ni]);
        }

        __syncthreads();
        if (it + 2 < NIT) load_stage(st, (it + 2) * BK);
        cp_commit();
    }

#pragma unroll
    for (int mi = 0; mi < MT; mi++){
#pragma unroll
        for (int rr = 0; rr < 2; rr++){
            const int m = bm + wm * (BM/2) + mi * 16 + g + rr * 8;
#pragma unroll
            for (int ni = 0; ni < NT; ni++){
                const int n = bn + wn * (BN/2) + ni * 8 + t * 2;
                const size_t idx = (size_t)m * N + n;
                float v0 = acc[mi][ni][rr * 2 + 0];
                float v1 = acc[mi][ni][rr * 2 + 1];
                if (EPI == 1){
                    const float2 a2 = *(const float2*)(Cadd + idx);
                    v0 += a2.x; v1 += a2.y;
                }
                if (EPI == 2){
                    v0 = v0 > 0.f ? v0 * v0 : 0.f;
                    v1 = v1 > 0.f ? v1 * v1 : 0.f;
                    v0 = roundtf(v0); v1 = roundtf(v1);   // feeds next GEMM
                }
                if (EPI == 3){                            // fused value-residual mix
                    if (first){
                        v0 = roundtf(v0); v1 = roundtf(v1);
                        float2 o1; o1.x = v0; o1.y = v1;
                        *(float2*)(Vone + idx) = o1;
                    } else {
                        const float2 w1 = *(const float2*)(Vone + idx);
                        v0 = roundtf((1.f - lamVal) * v0 + lamVal * w1.x);
                        v1 = roundtf((1.f - lamVal) * v1 + lamVal * w1.y);
                    }
                }
                float2 o; o.x = v0; o.y = v1;
                *(float2*)(C + idx) = o;
            }
        }
    }
}

template<int BM, int BN, int EPI>
__global__ void __launch_bounds__(128)
gemm_mma(const float* __restrict__ A, const float* __restrict__ B,
         const float* __restrict__ Cadd, float* __restrict__ C, int N, int K){
    gemm_mma_body<BM, BN, EPI>(A, B, Cadd, C, N, K, nullptr, 0.f, 0);
}

// fused Q/K/V projection; z==2 (V) additionally applies the value-residual mix
__global__ void __launch_bounds__(128)
gemm_mma3(const float* __restrict__ A,
          const float* __restrict__ B0, const float* __restrict__ B1, const float* __restrict__ B2,
          float* __restrict__ C0, float* __restrict__ C1, float* __restrict__ C2,
          float* __restrict__ Vone, const float* __restrict__ lamb, int layer, int first,
          int N, int K){
    if (blockIdx.z == 0){
        gemm_mma_body<128, 64, 0>(A, B0, nullptr, C0, N, K, nullptr, 0.f, 0);
    } else if (blockIdx.z == 1){
        gemm_mma_body<128, 64, 0>(A, B1, nullptr, C1, N, K, nullptr, 0.f, 0);
    } else {
        const float l = first ? 0.f : lamb[layer];
        gemm_mma_body<128, 64, 3>(A, B2, nullptr, C2, N, K, Vone, l, first);
    }
}

// ---------------- mask prefix (cumsum of levels==0) ------------------------
__global__ void build_cpad(const int* __restrict__ levels, int* __restrict__ cpad){
    __shared__ int sbuf[S_];
    int t = threadIdx.x;
    sbuf[t] = (levels[t] == 0) ? 1 : 0;
    __syncthreads();
    for (int off = 1; off < S_; off <<= 1){
        int v = 0;
        if (t >= off) v = sbuf[t - off];
        __syncthreads();
        sbuf[t] += v;
        __syncthreads();
    }
    cpad[t+1] = sbuf[t];
    if (t == 0) cpad[0] = 0;
}

// ---------------- row RMS norm (ROUND: tf32-round the output) ---------------
template<int ROUND>
__global__ void rms_kernel(const float* __restrict__ in, float* __restrict__ out,
                           float* __restrict__ out2){
    __shared__ float red[256];
    const int row = blockIdx.x;
    const int t = threadIdx.x;
    const float* r = in + (size_t)row * D_;
    float v[4]; float ss = 0.f;
#pragma unroll
    for (int j = 0; j < 4; j++){ v[j] = r[t + j*256]; ss += v[j]*v[j]; }
    red[t] = ss; __syncthreads();
    for (int o = 128; o > 0; o >>= 1){ if (t < o) red[t] += red[t+o]; __syncthreads(); }
    const float sc = rsqrtf(red[0] * (1.f/D_) + EPS_);
    float* o1 = out + (size_t)row * D_;
#pragma unroll
    for (int j = 0; j < 4; j++){
        float w = v[j] * sc;
        o1[t + j*256] = ROUND ? roundtf(w) : w;
        if (out2) out2[(size_t)row*D_ + t + j*256] = w;
    }
}

// ---------------- xl = l0*x + l1*x0 ; xn = round(rms(xl)) -------------------
__global__ void mix_rms_kernel(const float* __restrict__ x, const float* __restrict__ x0,
                               const float* __restrict__ lambdas, int layer,
                               float* __restrict__ xl, float* __restrict__ xn){
    __shared__ float red[256];
    const int row = blockIdx.x;
    const int t = threadIdx.x;
    const float l0 = lambdas[2*layer + 0];
    const float l1 = lambdas[2*layer + 1];
    float v[4]; float ss = 0.f;
#pragma unroll
    for (int j = 0; j < 4; j++){
        size_t idx = (size_t)row*D_ + t + j*256;
        float w = l0 * x[idx] + l1 * x0[idx];
        v[j] = w; xl[idx] = w; ss += w*w;
    }
    red[t] = ss; __syncthreads();
    for (int o = 128; o > 0; o >>= 1){ if (t < o) red[t] += red[t+o]; __syncthreads(); }
    const float sc = rsqrtf(red[0] * (1.f/D_) + EPS_);
#pragma unroll
    for (int j = 0; j < 4; j++){
        size_t idx = (size_t)row*D_ + t + j*256;
        xn[idx] = roundtf(v[j] * sc);
    }
}

// ---------------- per-head RMS + RoPE on q and k (rounds outputs) -----------
__global__ void qk_rmsrope(float* __restrict__ q, float* __restrict__ k){
    const int gw   = (blockIdx.x * blockDim.x + threadIdx.x) >> 5;
    const int lane = threadIdx.x & 31;
    const int t = gw >> 4;
    const int h = gw & 15;

    const float inv = expf(-((float)(2*lane) / 64.f) * logf(10000.f));
    const float fr  = (float)t * inv;
    float sn, cs;
    sincosf(fr, &sn, &cs);

    float* bases[2] = { q + (size_t)t*D_ + h*HD_, k + (size_t)t*D_ + h*HD_ };
#pragma unroll
    for (int p = 0; p < 2; p++){
        float* r = bases[p];
        float x1 = r[lane];
        float x2 = r[lane + 32];
        float ss = x1*x1 + x2*x2;
#pragma unroll
        for (int off = 16; off > 0; off >>= 1)
            ss += __shfl_xor_sync(0xffffffffu, ss, off);
        float sc = rsqrtf(ss * (1.f/HD_) + EPS_);
        x1 *= sc; x2 *= sc;
        r[lane]      = roundtf( x1*cs + x2*sn);
        r[lane + 32] = roundtf(-x1*sn + x2*cs);
    }
}

// ---------------- masked scores via tf32 mma: S[h][q][k] --------------------
__global__ void __launch_bounds__(128)
attn_scores_mma(const float* __restrict__ q, const float* __restrict__ k,
                const int* __restrict__ levels, const int* __restrict__ samp,
                const int* __restrict__ cpad, float* __restrict__ scores){
    const int h = blockIdx.z, qt = blockIdx.y, kt = blockIdx.x;
    if (kt > qt) return;                    // upper tiles never read downstream

    __shared__ float Qs[64][68];
    __shared__ float Ks[64][68];
    __shared__ int sq[64], cq[64], sk[64], ck1[64];
    __shared__ int lk0[64];

    const int tid = threadIdx.x;
    for (int i = tid; i < 1024; i += 128){
        int r = i >> 4, c = (i & 15) << 2;
        *(float4*)&Qs[r][c] = *(const float4*)(q + (size_t)(qt*64 + r)*D_ + h*HD_ + c);
        *(float4*)&Ks[r][c] = *(const float4*)(k + (size_t)(kt*64 + r)*D_ + h*HD_ + c);
    }
    if (tid < 64){
        int qq = qt*64 + tid, kk = kt*64 + tid;
        sq[tid] = samp[qq]; cq[tid] = cpad[qq];
        sk[tid] = samp[kk]; ck1[tid] = cpad[kk+1];
        lk0[tid] = (levels[kk] == 0);
    }
    __syncthreads();

    const int warp = tid >> 5, lane = tid & 31;
    const int g = lane >> 2, t = lane & 3;
    const int r0 = warp*16 + g;

    float acc[8][4];
#pragma unroll
    for (int i = 0; i < 8; i++)
#pragma unroll
        for (int c = 0; c < 4; c++) acc[i][c] = 0.f;

#pragma unroll
    for (int ks = 0; ks < 8; ks++){
        const int kb = ks*8;
        uint32_t A[4] = {
            __float_as_uint(Qs[r0    ][kb+t  ]),
            __float_as_uint(Qs[r0 + 8][kb+t  ]),
            __float_as_uint(Qs[r0    ][kb+t+4]),
            __float_as_uint(Qs[r0 + 8][kb+t+4]) };
#pragma unroll
        for (int ni = 0; ni < 8; ni++){
            uint32_t B[2] = {
                __float_as_uint(Ks[ni*8+g][kb+t  ]),
                __float_as_uint(Ks[ni*8+g][kb+t+4]) };
            mma_tf32(acc[ni], A, B);
        }
    }

    float* Sp = scores + ((size_t)h*S_ + qt*64)*(size_t)S_ + kt*64;
#pragma unroll
    for (int ni = 0; ni < 8; ni++){
#pragma unroll
        for (int rr = 0; rr < 2; rr++){
            const int m = warp*16 + g + rr*8;
            const int n0 = ni*8 + t*2;
            const int qq = qt*64 + m;
            float2 o;
#pragma unroll
            for (int cc = 0; cc < 2; cc++){
                const int n = n0 + cc;
                const int kk = kt*64 + n;
                bool ok = (kk <= qq) && (sk[n] == sq[m])
                       && !(lk0[n] && (cq[m] - ck1[n] > 0));
                float val = ok ? acc[ni][rr*2+cc] * 0.125f : -1e30f;
                (cc ? o.y : o.x) = val;
            }
            *(float2*)(Sp + (size_t)m*S_ + n0) = o;
        }
    }
}

// ---------------- row softmax over causal prefix only; rounds P -------------
__global__ void softmax_kernel(float* __restrict__ sc){
    __shared__ float red[256];
    const int row = blockIdx.x;                 // h*S + q
    const int qpos = row & (S_-1);
    const int kmax = ((qpos >> 6) + 1) << 6;
    float* p = sc + (size_t)row * S_;
    const int t = threadIdx.x;
    float v[4];
    float mx = -1e38f;
#pragma unroll
    for (int j = 0; j < 4; j++){
        int idx = t + j*256;
        v[j] = (idx < kmax) ? p[idx] : -1e38f;
        mx = fmaxf(mx, v[j]);
    }
    red[t] = mx; __syncthreads();
    for (int o = 128; o > 0; o >>= 1){ if (t < o) red[t] = fmaxf(red[t], red[t+o]); __syncthreads(); }
    mx = red[0]; __syncthreads();
    float s = 0.f;
#pragma unroll
    for (int j = 0; j < 4; j++){
        int idx = t + j*256;
        v[j] = (idx < kmax) ? __expf(v[j] - mx) : 0.f;
        s += v[j];
    }
    red[t] = s; __syncthreads();
    for (int o = 128; o > 0; o >>= 1){ if (t < o) red[t] += red[t+o]; __syncthreads(); }
    const float inv = 1.f / red[0];
#pragma unroll
    for (int j = 0; j < 4; j++){
        int idx = t + j*256;
        if (idx < kmax) p[idx] = roundtf(v[j] * inv);
    }
}

// ---------------- y = P @ V via tf32 mma (causal K range only) --------------
__global__ void __launch_bounds__(128)
attn_pv(const float* __restrict__ P, const float* __restrict__ v, float* __restrict__ y){
    const int h = blockIdx.y, qt = blockIdx.x;
    __shared__ float Ps[64][36];
    __shared__ float Vt[64][35];        // [n(dim)][k(token)] transposed

    const int tid = threadIdx.x;
    const int warp = tid >> 5, lane = tid & 31;
    const int g = lane >> 2, t = lane & 3;
    const int r0 = warp*16 + g;
    const float* Pp = P + ((size_t)h*S_ + qt*64)*(size_t)S_;
    const int kmax = (qt + 1) * 64;

    float acc[8][4];
#pragma unroll
    for (int i = 0; i < 8; i++)
#pragma unroll
        for (int c = 0; c < 4; c++) acc[i][c] = 0.f;

    for (int k0 = 0; k0 < kmax; k0 += 32){
        for (int i = tid; i < 512; i += 128){
            int r = i >> 3, c = (i & 7) << 2;
            *(float4*)&Ps[r][c] = *(const float4*)(Pp + (size_t)r*S_ + k0 + c);
        }
        for (int i = tid; i < 512; i += 128){
            int kk = i >> 4, c = (i & 15) << 2;
            float4 vv = *(const float4*)(v + (size_t)(k0+kk)*D_ + h*HD_ + c);
            Vt[c+0][kk] = vv.x; Vt[c+1][kk] = vv.y;
            Vt[c+2][kk] = vv.z; Vt[c+3][kk] = vv.w;
        }
        __syncthreads();

#pragma unroll
        for (int ks = 0; ks < 4; ks++){
            const int kb = ks*8;
            uint32_t A[4] = {
                __float_as_uint(Ps[r0    ][kb+t  ]),
                __float_as_uint(Ps[r0 + 8][kb+t  ]),
                __float_as_uint(Ps[r0    ][kb+t+4]),
                __float_as_uint(Ps[r0 + 8][kb+t+4]) };
#pragma unroll
            for (int ni = 0; ni < 8; ni++){
                uint32_t B[2] = {
                    __float_as_uint(Vt[ni*8+g][kb+t  ]),
                    __float_as_uint(Vt[ni*8+g][kb+t+4]) };
                mma_tf32(acc[ni], A, B);
            }
        }
        __syncthreads();
    }

#pragma unroll
    for (int ni = 0; ni < 8; ni++){
#pragma unroll
        for (int rr = 0; rr < 2; rr++){
            const int m = warp*16 + g + rr*8;
            const int n0 = ni*8 + t*2;
            float2 o;
            o.x = roundtf(acc[ni][rr*2+0]);     // y feeds the Wo GEMM
            o.y = roundtf(acc[ni][rr*2+1]);
            *(float2*)(y + (size_t)(qt*64 + m)*D_ + h*HD_ + n0) = o;
        }
    }
}

// ---------------------------------------------------------------------------
extern "C" void kernel_launch(void* const* d_in, const int* in_sizes, int n_in,
                              void* d_out, int out_size){
    const float* x_in   = (const float*)d_in[0];
    const float* Wq     = (const float*)d_in[1];
    const float* Wk     = (const float*)d_in[2];
    const float* Wv     = (const float*)d_in[3];
    const float* Wo     = (const float*)d_in[4];
    const float* lamb   = (const float*)d_in[5];
    const float* lambdas= (const float*)d_in[6];
    const float* Wfc    = (const float*)d_in[7];
    const float* Wp     = (const float*)d_in[8];
    const int*   levels = (const int*)d_in[9];
    const int*   sidx   = (const int*)d_in[10];
    float* out = (float*)d_out;

    float *px,*px0,*pxl,*pxn,*pq,*pk,*pv,*pv1,*py,*ph,*psc; int* pcpad;
    cudaGetSymbolAddress((void**)&px,  g_x);
    cudaGetSymbolAddress((void**)&px0, g_x0);
    cudaGetSymbolAddress((void**)&pxl, g_xl);
    cudaGetSymbolAddress((void**)&pxn, g_xn);
    cudaGetSymbolAddress((void**)&pq,  g_q);
    cudaGetSymbolAddress((void**)&pk,  g_k);
    cudaGetSymbolAddress((void**)&pv,  g_v);
    cudaGetSymbolAddress((void**)&pv1, g_v1);
    cudaGetSymbolAddress((void**)&py,  g_y);
    cudaGetSymbolAddress((void**)&ph,  g_h);
    cudaGetSymbolAddress((void**)&psc, g_sc);
    cudaGetSymbolAddress((void**)&pcpad, g_cpad);

    build_cpad<<<1, 1024>>>(levels, pcpad);
    rms_kernel<0><<<S_, 256>>>(x_in, px, px0);        // x = rms(x); x0 = x

    for (int i = 0; i < NL_; i++){
        mix_rms_kernel<<<S_, 256>>>(px, px0, lambdas, i, pxl, pxn);

        // fused q/k/v projections + value-residual mix in the V epilogue
        gemm_mma3<<<dim3(D_/64, S_/128, 3), 128>>>(
            pxn, Wq + (size_t)i*DD_, Wk + (size_t)i*DD_, Wv + (size_t)i*DD_,
            pq, pk, pv, pv1, lamb, i, (i == 0) ? 1 : 0, D_, D_);

        qk_rmsrope<<<(S_*H_*32)/256, 256>>>(pq, pk);

        attn_scores_mma<<<dim3(16, 16, 16), 128>>>(pq, pk, levels, sidx, pcpad, psc);
        softmax_kernel<<<H_*S_, 256>>>(psc);
        attn_pv<<<dim3(16, 16), 128>>>(psc, pv, py);

        gemm_mma<128,64,1><<<dim3(D_/64, S_/128), 128>>>(
            py, Wo + (size_t)i*DD_, pxl, px, D_, D_);

        rms_kernel<1><<<S_, 256>>>(px, pxn, nullptr);
        gemm_mma<128,64,2><<<dim3(DFF_/64, S_/128), 128>>>(
            pxn, Wfc + (size_t)i*DFD_, nullptr, ph, DFF_, D_);
        gemm_mma<128,64,1><<<dim3(D_/64, S_/128), 128>>>(
            ph, Wp + (size_t)i*DFD_, px, px, D_, DFF_);
    }

    rms_kernel<0><<<S_, 256>>>(px, out, nullptr);
}

// round 16
// speedup vs baseline: 3.3391x; 1.3408x over previous
#include <cuda_runtime.h>
#include <cuda_fp16.h>
#include <math.h>
#include <stdint.h>

// Problem dims (fixed by the reference)
static constexpr int S_   = 1024;
static constexpr int D_   = 1024;
static constexpr int H_   = 16;
static constexpr int HD_  = 64;
static constexpr int NL_  = 6;
static constexpr int DFF_ = 4096;
static constexpr float EPS_ = 1.1920929e-07f;

static constexpr size_t DD_  = (size_t)D_ * D_;        // 1M
static constexpr size_t DFD_ = (size_t)DFF_ * D_;      // 4M

// ---------------- scratch (static device globals; no allocations) ----------
__device__ float  g_x  [S_*D_];
__device__ float  g_x0 [S_*D_];
__device__ float  g_xl [S_*D_];
__device__ __half g_xnh[S_*D_];
__device__ float  g_q  [S_*D_];
__device__ float  g_k  [S_*D_];
__device__ float  g_v  [S_*D_];
__device__ float  g_v1 [S_*D_];
__device__ __half g_yh [S_*D_];
__device__ __half g_hh [S_*DFF_];
__device__ float  g_sc [(size_t)H_*S_*S_];   // 64 MB scores/probs
__device__ int    g_cpad[S_+1];

// =================== small PTX helpers (baseline ISA only) ==================
__device__ __forceinline__ uint32_t s2u(const void* p){
    return (uint32_t)__cvta_generic_to_shared(p);
}
__device__ __forceinline__ void cp_async16(void* smem_dst, const void* gsrc){
    asm volatile("cp.async.cg.shared.global [%0], [%1], 16;"
                 :: "r"(s2u(smem_dst)), "l"(gsrc) : "memory");
}
__device__ __forceinline__ void cp_commit(){
    asm volatile("cp.async.commit_group;" ::: "memory");
}
__device__ __forceinline__ void cp_wait1(){
    asm volatile("cp.async.wait_group 1;" ::: "memory");
}
__device__ __forceinline__ uint32_t f2tf32(float x){
    uint32_t y;
    asm("cvt.rna.tf32.f32 %0, %1;" : "=r"(y) : "f"(x));
    return y;
}
__device__ __forceinline__ float roundtf(float x){
    return __uint_as_float(f2tf32(x));
}
__device__ __forceinline__ void mma_tf32(float c[4], const uint32_t a[4], const uint32_t b[2]){
    asm volatile(
        "mma.sync.aligned.m16n8k8.row.col.f32.tf32.tf32.f32 "
        "{%0,%1,%2,%3}, {%4,%5,%6,%7}, {%8,%9}, {%0,%1,%2,%3};"
        : "+f"(c[0]), "+f"(c[1]), "+f"(c[2]), "+f"(c[3])
        : "r"(a[0]), "r"(a[1]), "r"(a[2]), "r"(a[3]), "r"(b[0]), "r"(b[1]));
}
__device__ __forceinline__ void mma_f16(float c[4], const uint32_t a[4], const uint32_t b[2]){
    asm volatile(
        "mma.sync.aligned.m16n8k16.row.col.f32.f16.f16.f32 "
        "{%0,%1,%2,%3}, {%4,%5,%6,%7}, {%8,%9}, {%0,%1,%2,%3};"
        : "+f"(c[0]), "+f"(c[1]), "+f"(c[2]), "+f"(c[3])
        : "r"(a[0]), "r"(a[1]), "r"(a[2]), "r"(a[3]), "r"(b[0]), "r"(b[1]));
}
__device__ __forceinline__ void ldsm_x4(uint32_t r[4], uint32_t addr){
    asm volatile("ldmatrix.sync.aligned.m8n8.x4.shared.b16 {%0,%1,%2,%3}, [%4];"
                 : "=r"(r[0]), "=r"(r[1]), "=r"(r[2]), "=r"(r[3]) : "r"(addr));
}
__device__ __forceinline__ uint32_t packh2(float lo, float hi){
    __half2 h = __floats2half2_rn(lo, hi);
    return *(uint32_t*)&h;
}

// ========== fp16 mma NT GEMM: C[M,N] = A[M,K](half) @ B[N,K](f32)^T =========
// CTA 128x64, 256 threads = 8 warps as 4(M) x 2(N); warp tile 32x32.
// A fragments via ldmatrix (conflict-free 80B stride); B (weights) packed
// f32->f16x2 at fragment load (one LDS.64 + one cvt per b-reg).
// EPI: 0=none (f32 C), 1=C=acc+Cadd (f32), 2=Ch=half(relu(acc)^2), 3=V-mix
template<int EPI>
__device__ __forceinline__ void gemm_f16_body(
    const __half* __restrict__ A, const float* __restrict__ B,
    const float* __restrict__ Cadd, float* __restrict__ C, __half* __restrict__ Ch,
    int N, int K, float* __restrict__ Vone, float lamVal, int first)
{
    constexpr int BM = 128, BN = 64, BK = 32;
    constexpr int RSA = 40;     // halfs  (80B rows:  5 mod 8 -> conflict-free ldmatrix)
    constexpr int RSB = 40;     // floats (160B rows: phase-conflict-free LDS.64)

    __shared__ __half As[2][BM * RSA];
    __shared__ float  Bs[2][BN * RSB];

    const int tid  = threadIdx.x;
    const int lane = tid & 31;
    const int warp = tid >> 5;
    const int wm   = warp >> 1;           // 0..3
    const int wn   = warp & 1;            // 0..1
    const int g    = lane >> 2;           // 0..7
    const int t    = lane & 3;            // 0..3

    const int bm = blockIdx.y * BM;
    const int bn = blockIdx.x * BN;
    const int NIT = K / BK;

    float acc[2][4][4];
#pragma unroll
    for (int i = 0; i < 2; i++)
#pragma unroll
        for (int j = 0; j < 4; j++)
#pragma unroll
            for (int c = 0; c < 4; c++) acc[i][j][c] = 0.f;

    auto load_stage = [&](int st, int k0){
#pragma unroll
        for (int i = 0; i < 2; i++){                    // A: 512 chunks of 8 halfs
            int s = tid + i * 256;
            int r = s >> 2, c8 = (s & 3) << 3;
            cp_async16(&As[st][r * RSA + c8], A + (size_t)(bm + r) * K + k0 + c8);
        }
#pragma unroll
        for (int i = 0; i < 2; i++){                    // B: 512 chunks of 4 floats
            int s = tid + i * 256;
            int r = s >> 3, c4 = (s & 7) << 2;
            cp_async16(&Bs[st][r * RSB + c4], B + (size_t)(bn + r) * K + k0 + c4);
        }
    };

    load_stage(0, 0);        cp_commit();
    load_stage(1, BK);       cp_commit();

    // per-thread ldmatrix row/col pattern (constant across iters)
    const int lrow = lane & 15;                 // row offset within 16
    const int lcol = (lane >> 4) << 3;          // 0 or 8 (halfs)

    for (int it = 0; it < NIT; ++it){
        const int st = it & 1;
        cp_wait1();
        __syncthreads();

#pragma unroll
        for (int ks = 0; ks < 2; ks++){
            const int kb = ks * 16;
            uint32_t af[2][4];
#pragma unroll
            for (int mi = 0; mi < 2; mi++){
                const int r0 = wm * 32 + mi * 16;
                ldsm_x4(af[mi], s2u(&As[st][(r0 + lrow) * RSA + kb + lcol]));
            }
            uint32_t bf[4][2];
#pragma unroll
            for (int ni = 0; ni < 4; ni++){
                const float* bp = &Bs[st][(wn * 32 + ni * 8 + g) * RSB + kb + 2 * t];
                float2 b0 = *(const float2*)bp;
                float2 b1 = *(const float2*)(bp + 8);
                bf[ni][0] = packh2(b0.x, b0.y);
                bf[ni][1] = packh2(b1.x, b1.y);
            }
#pragma unroll
            for (int mi = 0; mi < 2; mi++)
#pragma unroll
                for (int ni = 0; ni < 4; ni++)
                    mma_f16(acc[mi][ni], af[mi], bf[ni]);
        }

        __syncthreads();
        if (it + 2 < NIT) load_stage(st, (it + 2) * BK);
        cp_commit();
    }

#pragma unroll
    for (int mi = 0; mi < 2; mi++){
#pragma unroll
        for (int rr = 0; rr < 2; rr++){
            const int m = bm + wm * 32 + mi * 16 + g + rr * 8;
#pragma unroll
            for (int ni = 0; ni < 4; ni++){
                const int n = bn + wn * 32 + ni * 8 + t * 2;
                const size_t idx = (size_t)m * N + n;
                float v0 = acc[mi][ni][rr * 2 + 0];
                float v1 = acc[mi][ni][rr * 2 + 1];
                if (EPI == 1){
                    const float2 a2 = *(const float2*)(Cadd + idx);
                    v0 += a2.x; v1 += a2.y;
                    float2 o; o.x = v0; o.y = v1;
                    *(float2*)(C + idx) = o;
                } else if (EPI == 2){
                    v0 = v0 > 0.f ? v0 * v0 : 0.f;
                    v1 = v1 > 0.f ? v1 * v1 : 0.f;
                    *(__half2*)(Ch + idx) = __floats2half2_rn(v0, v1);
                } else if (EPI == 3){
                    if (first){
                        v0 = roundtf(v0); v1 = roundtf(v1);
                        float2 o1; o1.x = v0; o1.y = v1;
                        *(float2*)(Vone + idx) = o1;
                    } else {
                        const float2 w1 = *(const float2*)(Vone + idx);
                        v0 = roundtf((1.f - lamVal) * v0 + lamVal * w1.x);
                        v1 = roundtf((1.f - lamVal) * v1 + lamVal * w1.y);
                    }
                    float2 o; o.x = v0; o.y = v1;
                    *(float2*)(C + idx) = o;
                } else {
                    float2 o; o.x = v0; o.y = v1;
                    *(float2*)(C + idx) = o;
                }
            }
        }
    }
}

template<int EPI>
__global__ void __launch_bounds__(256)
gemm_f16(const __half* __restrict__ A, const float* __restrict__ B,
         const float* __restrict__ Cadd, float* __restrict__ C, __half* __restrict__ Ch,
         int N, int K){
    gemm_f16_body<EPI>(A, B, Cadd, C, Ch, N, K, nullptr, 0.f, 0);
}

// fused Q/K/V projection; z==2 (V) additionally applies the value-residual mix
__global__ void __launch_bounds__(256)
gemm_f16_qkv(const __half* __restrict__ A,
             const float* __restrict__ B0, const float* __restrict__ B1, const float* __restrict__ B2,
             float* __restrict__ C0, float* __restrict__ C1, float* __restrict__ C2,
             float* __restrict__ Vone, const float* __restrict__ lamb, int layer, int first,
             int N, int K){
    if (blockIdx.z == 0){
        gemm_f16_body<0>(A, B0, nullptr, C0, nullptr, N, K, nullptr, 0.f, 0);
    } else if (blockIdx.z == 1){
        gemm_f16_body<0>(A, B1, nullptr, C1, nullptr, N, K, nullptr, 0.f, 0);
    } else {
        const float l = first ? 0.f : lamb[layer];
        gemm_f16_body<3>(A, B2, nullptr, C2, nullptr, N, K, Vone, l, first);
    }
}

// ---------------- mask prefix (cumsum of levels==0) ------------------------
__global__ void build_cpad(const int* __restrict__ levels, int* __restrict__ cpad){
    __shared__ int sbuf[S_];
    int t = threadIdx.x;
    sbuf[t] = (levels[t] == 0) ? 1 : 0;
    __syncthreads();
    for (int off = 1; off < S_; off <<= 1){
        int v = 0;
        if (t >= off) v = sbuf[t - off];
        __syncthreads();
        sbuf[t] += v;
        __syncthreads();
    }
    cpad[t+1] = sbuf[t];
    if (t == 0) cpad[0] = 0;
}

// ---------------- row RMS norm, fp32 out (+optional copy) -------------------
__global__ void rms_f32(const float* __restrict__ in, float* __restrict__ out,
                        float* __restrict__ out2){
    __shared__ float red[256];
    const int row = blockIdx.x;
    const int t = threadIdx.x;
    const float* r = in + (size_t)row * D_;
    float v[4]; float ss = 0.f;
#pragma unroll
    for (int j = 0; j < 4; j++){ v[j] = r[t + j*256]; ss += v[j]*v[j]; }
    red[t] = ss; __syncthreads();
    for (int o = 128; o > 0; o >>= 1){ if (t < o) red[t] += red[t+o]; __syncthreads(); }
    const float sc = rsqrtf(red[0] * (1.f/D_) + EPS_);
    float* o1 = out + (size_t)row * D_;
#pragma unroll
    for (int j = 0; j < 4; j++){
        float w = v[j] * sc;
        o1[t + j*256] = w;
        if (out2) out2[(size_t)row*D_ + t + j*256] = w;
    }
}

// ---------------- row RMS norm, half out ------------------------------------
__global__ void rms_h(const float* __restrict__ in, __half* __restrict__ out){
    __shared__ float red[256];
    const int row = blockIdx.x;
    const int t = threadIdx.x;
    const float* r = in + (size_t)row * D_;
    float v[4]; float ss = 0.f;
#pragma unroll
    for (int j = 0; j < 4; j++){ v[j] = r[t + j*256]; ss += v[j]*v[j]; }
    red[t] = ss; __syncthreads();
    for (int o = 128; o > 0; o >>= 1){ if (t < o) red[t] += red[t+o]; __syncthreads(); }
    const float sc = rsqrtf(red[0] * (1.f/D_) + EPS_);
    __half* o1 = out + (size_t)row * D_;
#pragma unroll
    for (int j = 0; j < 4; j++)
        o1[t + j*256] = __float2half_rn(v[j] * sc);
}

// ---------------- xl = l0*x + l1*x0 ; xn = half(rms(xl)) --------------------
__global__ void mix_rms_kernel(const float* __restrict__ x, const float* __restrict__ x0,
                               const float* __restrict__ lambdas, int layer,
                               float* __restrict__ xl, __half* __restrict__ xn){
    __shared__ float red[256];
    const int row = blockIdx.x;
    const int t = threadIdx.x;
    const float l0 = lambdas[2*layer + 0];
    const float l1 = lambdas[2*layer + 1];
    float v[4]; float ss = 0.f;
#pragma unroll
    for (int j = 0; j < 4; j++){
        size_t idx = (size_t)row*D_ + t + j*256;
        float w = l0 * x[idx] + l1 * x0[idx];
        v[j] = w; xl[idx] = w; ss += w*w;
    }
    red[t] = ss; __syncthreads();
    for (int o = 128; o > 0; o >>= 1){ if (t < o) red[t] += red[t+o]; __syncthreads(); }
    const float sc = rsqrtf(red[0] * (1.f/D_) + EPS_);
#pragma unroll
    for (int j = 0; j < 4; j++){
        size_t idx = (size_t)row*D_ + t + j*256;
        xn[idx] = __float2half_rn(v[j] * sc);
    }
}

// ---------------- per-head RMS + RoPE on q and k (rounds outputs) -----------
__global__ void qk_rmsrope(float* __restrict__ q, float* __restrict__ k){
    const int gw   = (blockIdx.x * blockDim.x + threadIdx.x) >> 5;
    const int lane = threadIdx.x & 31;
    const int t = gw >> 4;
    const int h = gw & 15;

    const float inv = expf(-((float)(2*lane) / 64.f) * logf(10000.f));
    const float fr  = (float)t * inv;
    float sn, cs;
    sincosf(fr, &sn, &cs);

    float* bases[2] = { q + (size_t)t*D_ + h*HD_, k + (size_t)t*D_ + h*HD_ };
#pragma unroll
    for (int p = 0; p < 2; p++){
        float* r = bases[p];
        float x1 = r[lane];
        float x2 = r[lane + 32];
        float ss = x1*x1 + x2*x2;
#pragma unroll
        for (int off = 16; off > 0; off >>= 1)
            ss += __shfl_xor_sync(0xffffffffu, ss, off);
        float sc = rsqrtf(ss * (1.f/HD_) + EPS_);
        x1 *= sc; x2 *= sc;
        r[lane]      = roundtf( x1*cs + x2*sn);
        r[lane + 32] = roundtf(-x1*sn + x2*cs);
    }
}

// ---------------- masked scores via tf32 mma: S[h][q][k] --------------------
__global__ void __launch_bounds__(128)
attn_scores_mma(const float* __restrict__ q, const float* __restrict__ k,
                const int* __restrict__ levels, const int* __restrict__ samp,
                const int* __restrict__ cpad, float* __restrict__ scores){
    const int h = blockIdx.z, qt = blockIdx.y, kt = blockIdx.x;
    if (kt > qt) return;                    // upper tiles never read downstream

    __shared__ float Qs[64][68];
    __shared__ float Ks[64][68];
    __shared__ int sq[64], cq[64], sk[64], ck1[64];
    __shared__ int lk0[64];

    const int tid = threadIdx.x;
    for (int i = tid; i < 1024; i += 128){
        int r = i >> 4, c = (i & 15) << 2;
        *(float4*)&Qs[r][c] = *(const float4*)(q + (size_t)(qt*64 + r)*D_ + h*HD_ + c);
        *(float4*)&Ks[r][c] = *(const float4*)(k + (size_t)(kt*64 + r)*D_ + h*HD_ + c);
    }
    if (tid < 64){
        int qq = qt*64 + tid, kk = kt*64 + tid;
        sq[tid] = samp[qq]; cq[tid] = cpad[qq];
        sk[tid] = samp[kk]; ck1[tid] = cpad[kk+1];
        lk0[tid] = (levels[kk] == 0);
    }
    __syncthreads();

    const int warp = tid >> 5, lane = tid & 31;
    const int g = lane >> 2, t = lane & 3;
    const int r0 = warp*16 + g;

    float acc[8][4];
#pragma unroll
    for (int i = 0; i < 8; i++)
#pragma unroll
        for (int c = 0; c < 4; c++) acc[i][c] = 0.f;

#pragma unroll
    for (int ks = 0; ks < 8; ks++){
        const int kb = ks*8;
        uint32_t A[4] = {
            __float_as_uint(Qs[r0    ][kb+t  ]),
            __float_as_uint(Qs[r0 + 8][kb+t  ]),
            __float_as_uint(Qs[r0    ][kb+t+4]),
            __float_as_uint(Qs[r0 + 8][kb+t+4]) };
#pragma unroll
        for (int ni = 0; ni < 8; ni++){
            uint32_t B[2] = {
                __float_as_uint(Ks[ni*8+g][kb+t  ]),
                __float_as_uint(Ks[ni*8+g][kb+t+4]) };
            mma_tf32(acc[ni], A, B);
        }
    }

    float* Sp = scores + ((size_t)h*S_ + qt*64)*(size_t)S_ + kt*64;
#pragma unroll
    for (int ni = 0; ni < 8; ni++){
#pragma unroll
        for (int rr = 0; rr < 2; rr++){
            const int m = warp*16 + g + rr*8;
            const int n0 = ni*8 + t*2;
            const int qq = qt*64 + m;
            float2 o;
#pragma unroll
            for (int cc = 0; cc < 2; cc++){
                const int n = n0 + cc;
                const int kk = kt*64 + n;
                bool ok = (kk <= qq) && (sk[n] == sq[m])
                       && !(lk0[n] && (cq[m] - ck1[n] > 0));
                float val = ok ? acc[ni][rr*2+cc] * 0.125f : -1e30f;
                (cc ? o.y : o.x) = val;
            }
            *(float2*)(Sp + (size_t)m*S_ + n0) = o;
        }
    }
}

// ---------------- row softmax over causal prefix only; rounds P -------------
__global__ void softmax_kernel(float* __restrict__ sc){
    __shared__ float red[256];
    const int row = blockIdx.x;                 // h*S + q
    const int qpos = row & (S_-1);
    const int kmax = ((qpos >> 6) + 1) << 6;
    float* p = sc + (size_t)row * S_;
    const int t = threadIdx.x;
    float v[4];
    float mx = -1e38f;
#pragma unroll
    for (int j = 0; j < 4; j++){
        int idx = t + j*256;
        v[j] = (idx < kmax) ? p[idx] : -1e38f;
        mx = fmaxf(mx, v[j]);
    }
    red[t] = mx; __syncthreads();
    for (int o = 128; o > 0; o >>= 1){ if (t < o) red[t] = fmaxf(red[t], red[t+o]); __syncthreads(); }
    mx = red[0]; __syncthreads();
    float s = 0.f;
#pragma unroll
    for (int j = 0; j < 4; j++){
        int idx = t + j*256;
        v[j] = (idx < kmax) ? __expf(v[j] - mx) : 0.f;
        s += v[j];
    }
    red[t] = s; __syncthreads();
    for (int o = 128; o > 0; o >>= 1){ if (t < o) red[t] += red[t+o]; __syncthreads(); }
    const float inv = 1.f / red[0];
#pragma unroll
    for (int j = 0; j < 4; j++){
        int idx = t + j*256;
        if (idx < kmax) p[idx] = roundtf(v[j] * inv);
    }
}

// ---------------- y = P @ V via tf32 mma (causal K range only) --------------
__global__ void __launch_bounds__(128)
attn_pv(const float* __restrict__ P, const float* __restrict__ v, __half* __restrict__ y){
    const int h = blockIdx.y, qt = blockIdx.x;
    __shared__ float Ps[64][36];
    __shared__ float Vt[64][35];        // [n(dim)][k(token)] transposed

    const int tid = threadIdx.x;
    const int warp = tid >> 5, lane = tid & 31;
    const int g = lane >> 2, t = lane & 3;
    const int r0 = warp*16 + g;
    const float* Pp = P + ((size_t)h*S_ + qt*64)*(size_t)S_;
    const int kmax = (qt + 1) * 64;

    float acc[8][4];
#pragma unroll
    for (int i = 0; i < 8; i++)
#pragma unroll
        for (int c = 0; c < 4; c++) acc[i][c] = 0.f;

    for (int k0 = 0; k0 < kmax; k0 += 32){
        for (int i = tid; i < 512; i += 128){
            int r = i >> 3, c = (i & 7) << 2;
            *(float4*)&Ps[r][c] = *(const float4*)(Pp + (size_t)r*S_ + k0 + c);
        }
        for (int i = tid; i < 512; i += 128){
            int kk = i >> 4, c = (i & 15) << 2;
            float4 vv = *(const float4*)(v + (size_t)(k0+kk)*D_ + h*HD_ + c);
            Vt[c+0][kk] = vv.x; Vt[c+1][kk] = vv.y;
            Vt[c+2][kk] = vv.z; Vt[c+3][kk] = vv.w;
        }
        __syncthreads();

#pragma unroll
        for (int ks = 0; ks < 4; ks++){
            const int kb = ks*8;
            uint32_t A[4] = {
                __float_as_uint(Ps[r0    ][kb+t  ]),
                __float_as_uint(Ps[r0 + 8][kb+t  ]),
                __float_as_uint(Ps[r0    ][kb+t+4]),
                __float_as_uint(Ps[r0 + 8][kb+t+4]) };
#pragma unroll
            for (int ni = 0; ni < 8; ni++){
                uint32_t B[2] = {
                    __float_as_uint(Vt[ni*8+g][kb+t  ]),
                    __float_as_uint(Vt[ni*8+g][kb+t+4]) };
                mma_tf32(acc[ni], A, B);
            }
        }
        __syncthreads();
    }

#pragma unroll
    for (int ni = 0; ni < 8; ni++){
#pragma unroll
        for (int rr = 0; rr < 2; rr++){
            const int m = warp*16 + g + rr*8;
            const int n0 = ni*8 + t*2;
            *(__half2*)(y + (size_t)(qt*64 + m)*D_ + h*HD_ + n0) =
                __floats2half2_rn(acc[ni][rr*2+0], acc[ni][rr*2+1]);
        }
    }
}

// ---------------------------------------------------------------------------
extern "C" void kernel_launch(void* const* d_in, const int* in_sizes, int n_in,
                              void* d_out, int out_size){
    const float* x_in   = (const float*)d_in[0];
    const float* Wq     = (const float*)d_in[1];
    const float* Wk     = (const float*)d_in[2];
    const float* Wv     = (const float*)d_in[3];
    const float* Wo     = (const float*)d_in[4];
    const float* lamb   = (const float*)d_in[5];
    const float* lambdas= (const float*)d_in[6];
    const float* Wfc    = (const float*)d_in[7];
    const float* Wp     = (const float*)d_in[8];
    const int*   levels = (const int*)d_in[9];
    const int*   sidx   = (const int*)d_in[10];
    float* out = (float*)d_out;

    float *px,*px0,*pxl,*pq,*pk,*pv,*pv1,*psc; int* pcpad;
    __half *pxnh,*pyh,*phh;
    cudaGetSymbolAddress((void**)&px,  g_x);
    cudaGetSymbolAddress((void**)&px0, g_x0);
    cudaGetSymbolAddress((void**)&pxl, g_xl);
    cudaGetSymbolAddress((void**)&pxnh,g_xnh);
    cudaGetSymbolAddress((void**)&pq,  g_q);
    cudaGetSymbolAddress((void**)&pk,  g_k);
    cudaGetSymbolAddress((void**)&pv,  g_v);
    cudaGetSymbolAddress((void**)&pv1, g_v1);
    cudaGetSymbolAddress((void**)&pyh, g_yh);
    cudaGetSymbolAddress((void**)&phh, g_hh);
    cudaGetSymbolAddress((void**)&psc, g_sc);
    cudaGetSymbolAddress((void**)&pcpad, g_cpad);

    build_cpad<<<1, 1024>>>(levels, pcpad);
    rms_f32<<<S_, 256>>>(x_in, px, px0);              // x = rms(x); x0 = x

    for (int i = 0; i < NL_; i++){
        mix_rms_kernel<<<S_, 256>>>(px, px0, lambdas, i, pxl, pxnh);

        // fused q/k/v projections (fp16 mma) + value-residual mix in V epilogue
        gemm_f16_qkv<<<dim3(D_/64, S_/128, 3), 256>>>(
            pxnh, Wq + (size_t)i*DD_, Wk + (size_t)i*DD_, Wv + (size_t)i*DD_,
            pq, pk, pv, pv1, lamb, i, (i == 0) ? 1 : 0, D_, D_);

        qk_rmsrope<<<(S_*H_*32)/256, 256>>>(pq, pk);

        attn_scores_mma<<<dim3(16, 16, 16), 128>>>(pq, pk, levels, sidx, pcpad, psc);
        softmax_kernel<<<H_*S_, 256>>>(psc);
        attn_pv<<<dim3(16, 16), 128>>>(psc, pv, pyh);

        // x = xl + y @ Wo^T
        gemm_f16<1><<<dim3(D_/64, S_/128), 256>>>(
            pyh, Wo + (size_t)i*DD_, pxl, px, nullptr, D_, D_);

        // MLP
        rms_h<<<S_, 256>>>(px, pxnh);
        gemm_f16<2><<<dim3(DFF_/64, S_/128), 256>>>(
            pxnh, Wfc + (size_t)i*DFD_, nullptr, nullptr, phh, DFF_, D_);
        gemm_f16<1><<<dim3(D_/64, S_/128), 256>>>(
            phh, Wp + (size_t)i*DFD_, px, px, nullptr, D_, DFF_);
    }

    rms_f32<<<S_, 256>>>(px, out, nullptr);
}